// round 6
// baseline (speedup 1.0000x reference)
#include <cuda_runtime.h>
#include <cuda_fp16.h>
#include <cstdint>

#define BB   8
#define CIN  64
#define CO   128
#define LL   18
#define LV   16
#define HW   1024
#define NH   2

// ---------------- scratch (device globals; no allocation allowed) ----------
__device__ float g_lp[(size_t)9*BB*NH*CO*CO];

__device__ __half g_Qh[(size_t)BB*CO*LL*HW];
__device__ __half g_Ql[(size_t)BB*CO*LL*HW];
__device__ __half g_Kh[(size_t)BB*CO*LL*HW];
__device__ __half g_Kl[(size_t)BB*CO*LL*HW];
__device__ __half g_Vh[(size_t)BB*CO*LV*HW];
__device__ __half g_Vl[(size_t)BB*CO*LV*HW];
__device__ __half g_aH[(size_t)BB*NH*CO*CO];
__device__ __half g_aL[(size_t)BB*NH*CO*CO];

__device__ __half g_hin[(size_t)BB*LL*HW*CIN];
__device__ __half g_lin[(size_t)BB*LL*HW*CIN];
__device__ __half g_hmm[(size_t)BB*LL*HW*CIN];
__device__ __half g_lmm[(size_t)BB*LL*HW*CIN];
__device__ uint4 g_wqh[9*1152],  g_wql[9*1152];
__device__ uint4 g_wkh[9*1152],  g_wkl[9*1152];
__device__ uint4 g_wvh[27*1152], g_wvl[27*1152];

// ---------------- PTX helpers ----------------------------------------------
__device__ __forceinline__ uint32_t smem_u32(const void* p) {
    uint32_t a;
    asm("{ .reg .u64 t; cvta.to.shared.u64 t, %1; cvt.u32.u64 %0, t; }"
        : "=r"(a) : "l"(p));
    return a;
}
__device__ __forceinline__ void ldmat4(uint32_t& r0, uint32_t& r1, uint32_t& r2,
                                       uint32_t& r3, uint32_t a) {
    asm volatile("ldmatrix.sync.aligned.m8n8.x4.shared.b16 {%0,%1,%2,%3}, [%4];"
                 : "=r"(r0), "=r"(r1), "=r"(r2), "=r"(r3) : "r"(a));
}
__device__ __forceinline__ void ldmat2(uint32_t& r0, uint32_t& r1, uint32_t a) {
    asm volatile("ldmatrix.sync.aligned.m8n8.x2.shared.b16 {%0,%1}, [%2];"
                 : "=r"(r0), "=r"(r1) : "r"(a));
}
__device__ __forceinline__ void ldmat2t(uint32_t& r0, uint32_t& r1, uint32_t a) {
    asm volatile("ldmatrix.sync.aligned.m8n8.x2.trans.shared.b16 {%0,%1}, [%2];"
                 : "=r"(r0), "=r"(r1) : "r"(a));
}
__device__ __forceinline__ void mma16816(float* c, const uint32_t* a,
                                         const uint32_t* b) {
    asm volatile(
        "mma.sync.aligned.m16n8k16.row.col.f32.f16.f16.f32 "
        "{%0,%1,%2,%3}, {%4,%5,%6,%7}, {%8,%9}, {%0,%1,%2,%3};"
        : "+f"(c[0]), "+f"(c[1]), "+f"(c[2]), "+f"(c[3])
        : "r"(a[0]), "r"(a[1]), "r"(a[2]), "r"(a[3]), "r"(b[0]), "r"(b[1]));
}
__device__ __forceinline__ void cpasync16(uint32_t dst, const void* src, int sz) {
    asm volatile("cp.async.ca.shared.global [%0], [%1], 16, %2;"
                 :: "r"(dst), "l"(src), "r"(sz) : "memory");
}
__device__ __forceinline__ void cp_commit() {
    asm volatile("cp.async.commit_group;" ::: "memory");
}
__device__ __forceinline__ void cp_wait1() {
    asm volatile("cp.async.wait_group 1;" ::: "memory");
}
__device__ __forceinline__ void cp_wait0() {
    asm volatile("cp.async.wait_group 0;" ::: "memory");
}

__device__ __forceinline__ void emit_split(__half* ph, __half* pl,
                                           float x, float y) {
    __half2 h, l;
    h.x = __float2half_rn(x);
    h.y = __float2half_rn(y);
    l.x = __float2half_rn(x - __half2float(h.x));
    l.y = __float2half_rn(y - __half2float(h.y));
    *(__half2*)ph = h;
    *(__half2*)pl = l;
}

// ---------------- prep kernels ---------------------------------------------
__global__ __launch_bounds__(256) void pack_k(const float* __restrict__ x, int dst) {
    __shared__ float tile[64][65];
    const int s = blockIdx.x;
    const int hw0 = blockIdx.y * 64;
    const int b = s / LL, l = s % LL;
    __half* oh = dst ? g_hmm : g_hin;
    __half* ol = dst ? g_lmm : g_lin;
#pragma unroll
    for (int i = 0; i < 16; i++) {
        int idx = threadIdx.x + i * 256;
        int ci = idx >> 6, hw = idx & 63;
        tile[ci][hw] = x[(((size_t)b * CIN + ci) * LL + l) * HW + hw0 + hw];
    }
    __syncthreads();
#pragma unroll
    for (int i = 0; i < 16; i++) {
        int idx = threadIdx.x + i * 256;
        int hw = idx >> 6, ci = idx & 63;
        float v = tile[ci][hw];
        __half h = __float2half_rn(v);
        size_t o = ((size_t)s * HW + hw0 + hw) * CIN + ci;
        oh[o] = h;
        ol[o] = __float2half_rn(v - __half2float(h));
    }
}

__global__ __launch_bounds__(256) void wprep_k(const float* __restrict__ w,
                                               int nchunk, int dst) {
    int i = blockIdx.x * 256 + threadIdx.x;
    if (i >= nchunk * 8192) return;
    int c = i >> 13, r = i & 8191, co = r >> 6, ci = r & 63;
    float v = w[(co * 64 + ci) * nchunk + c];
    __half h = __float2half_rn(v);
    __half lo = __float2half_rn(v - __half2float(h));
    __half *oh, *ol;
    if (dst == 0)      { oh = (__half*)g_wqh; ol = (__half*)g_wql; }
    else if (dst == 1) { oh = (__half*)g_wkh; ol = (__half*)g_wkl; }
    else               { oh = (__half*)g_wvh; ol = (__half*)g_wvl; }
    oh[(size_t)c * 9216 + co * 72 + ci] = h;
    ol[(size_t)c * 9216 + co * 72 + ci] = lo;
}

// ---------------- HMMA implicit-GEMM conv, 128co x 256px tiles -------------
#define ABYTES 18432
#define BPLANE 36864          // 256 rows * 144B
#define BUFSZ  110592         // A(hi+lo) + B(hi+lo)
#define SMEMSZ (2*BUFSZ)      // 221184

template<int NPASS>
__device__ __forceinline__ void issue_chunk(
    int c, int is3d, int p0, int b, int l, uint32_t sb,
    const uint4* wh, const uint4* wl,
    const __half* xh, const __half* xl, int tid) {
    int kd, kh, kw;
    if (is3d) { kd = c / 9; int r = c % 9; kh = r / 3; kw = r % 3; }
    else      { kd = 0; kh = c / 3; kw = c % 3; }
    const uint32_t base = sb + (c & 1) * BUFSZ;
    const int acop = (NPASS == 3) ? 2304 : 1152;
#pragma unroll
    for (int i = 0; i < 9; i++) {
        int idx = tid + i * 256;
        if (idx < acop) {
            int half_ = idx >= 1152;
            int r = idx - half_ * 1152;
            const uint4* s = (half_ ? wl : wh) + (size_t)c * 1152 + r;
            cpasync16(base + half_ * ABYTES + r * 16, s, 16);
        }
    }
#pragma unroll
    for (int i = 0; i < 2; i++) {
        int idx = tid + i * 256;
        int row = idx >> 1, sub = idx & 1;
        int pg = p0 + row;
        int ih = (pg >> 5) + kh - 1, iw = (pg & 31) + kw - 1;
        int ok = ((unsigned)ih < 32u) && ((unsigned)iw < 32u);
        int ihc = ok ? ih : 0, iwc = ok ? iw : 0;
        const __half* s = (sub ? xl : xh) +
            ((size_t)((b * LL + l + kd) * HW) + ihc * 32 + iwc) * CIN;
        uint32_t dst = base + 2 * ABYTES + sub * BPLANE + row * 144;
        int sz = ok ? 16 : 0;
#pragma unroll
        for (int j = 0; j < 8; j++)
            cpasync16(dst + j * 16, (const char*)s + j * 16, sz);
    }
    cp_commit();
}

template<int NPASS>
__global__ __launch_bounds__(256, 1)
void convmma_k(const float* __restrict__ bias, int mode, int DOUT, int NC,
               int is3d, float scale) {
    extern __shared__ char smem[];
    const uint32_t sb = smem_u32(smem);
    const int tid = threadIdx.x, wid = tid >> 5, lane = tid & 31;
    const int p0 = blockIdx.x * 256;
    const int b = blockIdx.y / DOUT, l = blockIdx.y % DOUT;

    const __half *xh, *xl;
    const uint4 *wh, *wl;
    __half *oph, *opl;
    if (mode == 0)      { xh = g_hin; xl = g_lin; wh = g_wqh; wl = g_wql;
                          oph = g_Qh; opl = g_Ql; }
    else if (mode == 1) { xh = g_hmm; xl = g_lmm; wh = g_wkh; wl = g_wkl;
                          oph = g_Kh; opl = g_Kl; }
    else                { xh = g_hmm; xl = g_lmm; wh = g_wvh; wl = g_wvl;
                          oph = g_Vh; opl = g_Vl; }

    const int co0 = (wid & 1) * 64;     // 2 warp rows over co
    const int p0l = (wid >> 1) * 64;    // 4 warp cols over 256 px

    float acc[4][8][4];
#pragma unroll
    for (int mt = 0; mt < 4; mt++)
#pragma unroll
        for (int nt = 0; nt < 8; nt++)
#pragma unroll
            for (int i = 0; i < 4; i++) acc[mt][nt][i] = 0.f;

    issue_chunk<NPASS>(0, is3d, p0, b, l, sb, wh, wl, xh, xl, tid);

    for (int c = 0; c < NC; c++) {
        if (c + 1 < NC) {
            issue_chunk<NPASS>(c + 1, is3d, p0, b, l, sb, wh, wl, xh, xl, tid);
            cp_wait1();
        } else {
            cp_wait0();
        }
        __syncthreads();
        const uint32_t base = sb + (c & 1) * BUFSZ;
        const uint32_t aAh = base, aAl = base + ABYTES;
        const uint32_t aBh = base + 2 * ABYTES, aBl = base + 2 * ABYTES + BPLANE;
#pragma unroll
        for (int k = 0; k < 4; k++) {
            uint32_t ah[4][4], al[4][4], bh[8][2], bl[8][2];
#pragma unroll
            for (int mt = 0; mt < 4; mt++) {
                uint32_t off = (uint32_t)(((co0 + mt * 16 + (lane & 15)) * 72 +
                                           k * 16 + (lane >> 4) * 8) * 2);
                ldmat4(ah[mt][0], ah[mt][1], ah[mt][2], ah[mt][3], aAh + off);
                if (NPASS == 3)
                    ldmat4(al[mt][0], al[mt][1], al[mt][2], al[mt][3], aAl + off);
            }
#pragma unroll
            for (int nt = 0; nt < 8; nt++) {
                uint32_t off = (uint32_t)(((p0l + nt * 8 + (lane & 7)) * 72 +
                                           k * 16 + ((lane >> 3) & 1) * 8) * 2);
                ldmat2(bh[nt][0], bh[nt][1], aBh + off);
                ldmat2(bl[nt][0], bl[nt][1], aBl + off);
            }
#pragma unroll
            for (int mt = 0; mt < 4; mt++)
#pragma unroll
                for (int nt = 0; nt < 8; nt++)
                    mma16816(acc[mt][nt], ah[mt], bh[nt]);
#pragma unroll
            for (int mt = 0; mt < 4; mt++)
#pragma unroll
                for (int nt = 0; nt < 8; nt++)
                    mma16816(acc[mt][nt], ah[mt], bl[nt]);
            if (NPASS == 3) {
#pragma unroll
                for (int mt = 0; mt < 4; mt++)
#pragma unroll
                    for (int nt = 0; nt < 8; nt++)
                        mma16816(acc[mt][nt], al[mt], bh[nt]);
            }
        }
        __syncthreads();
    }

#pragma unroll
    for (int mt = 0; mt < 4; mt++) {
        int co = co0 + mt * 16 + (lane >> 2);
        float bv0 = bias[co];
        float bv1 = bias[co + 8];
        size_t o0 = ((size_t)(b * CO + co) * DOUT + l) * HW + p0 + p0l;
        size_t o1 = o0 + (size_t)8 * DOUT * HW;
#pragma unroll
        for (int nt = 0; nt < 8; nt++) {
            int p = nt * 8 + (lane & 3) * 2;
            emit_split(oph + o0 + p, opl + o0 + p,
                       (acc[mt][nt][0] + bv0) * scale,
                       (acc[mt][nt][1] + bv0) * scale);
            emit_split(oph + o1 + p, opl + o1 + p,
                       (acc[mt][nt][2] + bv1) * scale,
                       (acc[mt][nt][3] + bv1) * scale);
        }
    }
}

// ---------------- logits: Q.K^T via HMMA, split-K over 9 l-slices ----------
#define LABYTES 18432
#define LBUFSZ  73728
#define LSMEMSZ (2*LBUFSZ)

__global__ __launch_bounds__(256, 1) void logits2_k() {
    extern __shared__ char smem[];
    const uint32_t sb = smem_u32(smem);
    const int tid = threadIdx.x, wid = tid >> 5, lane = tid & 31;
    const int lc = blockIdx.x, bn = blockIdx.y;
    const int b = bn >> 1, n = bn & 1;
    const int l = n * 9 + lc;

    const __half* srcs[4];
    srcs[0] = g_Qh + ((size_t)(b * CO) * LL + l) * HW;
    srcs[1] = g_Ql + ((size_t)(b * CO) * LL + l) * HW;
    srcs[2] = g_Kh + ((size_t)(b * CO) * LL + l) * HW;
    srcs[3] = g_Kl + ((size_t)(b * CO) * LL + l) * HW;

    const int co0 = (wid & 1) * 64;
    const int p0l = (wid >> 1) * 32;

    float acc[4][4][4];
#pragma unroll
    for (int mt = 0; mt < 4; mt++)
#pragma unroll
        for (int nt = 0; nt < 4; nt++)
#pragma unroll
            for (int i = 0; i < 4; i++) acc[mt][nt][i] = 0.f;

    auto issue = [&](int ch) {
        const uint32_t base = sb + (ch & 1) * LBUFSZ;
        const int hw0 = ch * 64;
#pragma unroll
        for (int r = tid; r < 512; r += 256) {
            int plane = r >> 7, c = r & 127;
            const __half* s = srcs[plane] + (size_t)c * (LL * HW) + hw0;
            uint32_t dst = base + plane * LABYTES + c * 144;
#pragma unroll
            for (int j = 0; j < 8; j++)
                cpasync16(dst + j * 16, (const char*)s + j * 16, 16);
        }
        cp_commit();
    };

    issue(0);
    for (int ch = 0; ch < 16; ch++) {
        if (ch + 1 < 16) { issue(ch + 1); cp_wait1(); }
        else             { cp_wait0(); }
        __syncthreads();
        const uint32_t base = sb + (ch & 1) * LBUFSZ;
        const uint32_t aAh = base, aAl = base + LABYTES;
        const uint32_t aBh = base + 2 * LABYTES, aBl = base + 3 * LABYTES;
#pragma unroll
        for (int k = 0; k < 4; k++) {
            uint32_t ah[4][4], al[4][4], bh[4][2], bl[4][2];
#pragma unroll
            for (int mt = 0; mt < 4; mt++) {
                uint32_t off = (uint32_t)(((co0 + mt * 16 + (lane & 15)) * 72 +
                                           k * 16 + (lane >> 4) * 8) * 2);
                ldmat4(ah[mt][0], ah[mt][1], ah[mt][2], ah[mt][3], aAh + off);
                ldmat4(al[mt][0], al[mt][1], al[mt][2], al[mt][3], aAl + off);
            }
#pragma unroll
            for (int nt = 0; nt < 4; nt++) {
                uint32_t off = (uint32_t)(((p0l + nt * 8 + (lane & 7)) * 72 +
                                           k * 16 + ((lane >> 3) & 1) * 8) * 2);
                ldmat2(bh[nt][0], bh[nt][1], aBh + off);
                ldmat2(bl[nt][0], bl[nt][1], aBl + off);
            }
#pragma unroll
            for (int mt = 0; mt < 4; mt++)
#pragma unroll
                for (int nt = 0; nt < 4; nt++)
                    mma16816(acc[mt][nt], ah[mt], bh[nt]);
#pragma unroll
            for (int mt = 0; mt < 4; mt++)
#pragma unroll
                for (int nt = 0; nt < 4; nt++)
                    mma16816(acc[mt][nt], ah[mt], bl[nt]);
#pragma unroll
            for (int mt = 0; mt < 4; mt++)
#pragma unroll
                for (int nt = 0; nt < 4; nt++)
                    mma16816(acc[mt][nt], al[mt], bh[nt]);
        }
        __syncthreads();
    }

    float* lp = g_lp + ((size_t)lc * 16 + bn) * CO * CO;
#pragma unroll
    for (int mt = 0; mt < 4; mt++) {
        int c = co0 + mt * 16 + (lane >> 2);
#pragma unroll
        for (int nt = 0; nt < 4; nt++) {
            int m = p0l + nt * 8 + (lane & 3) * 2;
            *(float2*)(lp + (size_t)c * CO + m) =
                make_float2(acc[mt][nt][0], acc[mt][nt][1]);
            *(float2*)(lp + (size_t)(c + 8) * CO + m) =
                make_float2(acc[mt][nt][2], acc[mt][nt][3]);
        }
    }
}

// ---------------- softmax ---------------------------------------------------
__global__ __launch_bounds__(256) void softmax_k() {
    const int warp = (blockIdx.x * 256 + threadIdx.x) >> 5;
    const int lane = threadIdx.x & 31;
    if (warp >= 16 * CO) return;
    const int bn = warp >> 7, c = warp & 127;
    float v[4];
#pragma unroll
    for (int j = 0; j < 4; j++) {
        int m = lane + j * 32;
        float s = 0.f;
#pragma unroll
        for (int p = 0; p < 9; p++)
            s += g_lp[(((size_t)p * 16 + bn) * CO + c) * CO + m];
        v[j] = s;
    }
    float mx = fmaxf(fmaxf(v[0], v[1]), fmaxf(v[2], v[3]));
#pragma unroll
    for (int o = 16; o; o >>= 1) mx = fmaxf(mx, __shfl_xor_sync(0xffffffffu, mx, o));
    float sum = 0.f;
#pragma unroll
    for (int j = 0; j < 4; j++) { v[j] = __expf(v[j] - mx); sum += v[j]; }
#pragma unroll
    for (int o = 16; o; o >>= 1) sum += __shfl_xor_sync(0xffffffffu, sum, o);
    float inv = 1.f / sum;
#pragma unroll
    for (int j = 0; j < 4; j++) {
        float a = v[j] * inv;
        __half h = __float2half_rn(a);
        size_t o = ((size_t)bn * CO + c) * CO + lane + j * 32;
        g_aH[o] = h;
        g_aL[o] = __float2half_rn(a - __half2float(h));
    }
}

// ---------------- out: attn x V via HMMA -----------------------------------
#define OPITCH 272
#define OTILE  34816
#define OSMEM  (4*OTILE)

__global__ __launch_bounds__(256, 1) void out2_k(float* __restrict__ out) {
    extern __shared__ char smem[];
    const uint32_t sb = smem_u32(smem);
    const int tid = threadIdx.x, wid = tid >> 5, lane = tid & 31;
    const int pt = blockIdx.x, b = blockIdx.y;
    const int l = pt >> 3;
    const int hw0 = (pt & 7) * 128;
    const int bn = b * 2 + (l >> 3);

    {
        int plane = tid >> 7, c = tid & 127;
        const __half* s =
            (plane ? g_aL : g_aH) + ((size_t)bn * CO + c) * CO;
        uint32_t dst = sb + plane * OTILE + c * OPITCH;
#pragma unroll
        for (int j = 0; j < 16; j++)
            cpasync16(dst + j * 16, (const char*)s + j * 16, 16);
        const __half* sv =
            (plane ? g_Vl : g_Vh) + ((size_t)(b * CO + c) * LV + l) * HW + hw0;
        uint32_t dv = sb + 2 * OTILE + plane * OTILE + c * OPITCH;
#pragma unroll
        for (int j = 0; j < 16; j++)
            cpasync16(dv + j * 16, (const char*)sv + j * 16, 16);
    }
    cp_commit();
    cp_wait0();
    __syncthreads();

    const int co0 = (wid & 1) * 64;
    const int p0l = (wid >> 1) * 32;
    const uint32_t aAh = sb, aAl = sb + OTILE;
    const uint32_t aBh = sb + 2 * OTILE, aBl = sb + 3 * OTILE;

    float acc[4][4][4];
#pragma unroll
    for (int mt = 0; mt < 4; mt++)
#pragma unroll
        for (int nt = 0; nt < 4; nt++)
#pragma unroll
            for (int i = 0; i < 4; i++) acc[mt][nt][i] = 0.f;

#pragma unroll
    for (int kc = 0; kc < 8; kc++) {
        uint32_t ah[4][4], al[4][4], bh[4][2], bl[4][2];
#pragma unroll
        for (int mt = 0; mt < 4; mt++) {
            uint32_t off = (uint32_t)((co0 + mt * 16 + (lane & 15)) * OPITCH +
                                      kc * 32 + (lane >> 4) * 16);
            ldmat4(ah[mt][0], ah[mt][1], ah[mt][2], ah[mt][3], aAh + off);
            ldmat4(al[mt][0], al[mt][1], al[mt][2], al[mt][3], aAl + off);
        }
#pragma unroll
        for (int nt = 0; nt < 4; nt++) {
            uint32_t off = (uint32_t)((kc * 16 + (lane & 15)) * OPITCH +
                                      (p0l + nt * 8) * 2);
            ldmat2t(bh[nt][0], bh[nt][1], aBh + off);
            ldmat2t(bl[nt][0], bl[nt][1], aBl + off);
        }
#pragma unroll
        for (int mt = 0; mt < 4; mt++)
#pragma unroll
            for (int nt = 0; nt < 4; nt++)
                mma16816(acc[mt][nt], ah[mt], bh[nt]);
#pragma unroll
        for (int mt = 0; mt < 4; mt++)
#pragma unroll
            for (int nt = 0; nt < 4; nt++)
                mma16816(acc[mt][nt], ah[mt], bl[nt]);
#pragma unroll
        for (int mt = 0; mt < 4; mt++)
#pragma unroll
            for (int nt = 0; nt < 4; nt++)
                mma16816(acc[mt][nt], al[mt], bh[nt]);
    }

#pragma unroll
    for (int mt = 0; mt < 4; mt++) {
        int c = co0 + mt * 16 + (lane >> 2);
        float* o0 = out + ((size_t)(b * CO + c) * LV + l) * HW + hw0 + p0l;
        float* o1 = o0 + (size_t)8 * LV * HW;
#pragma unroll
        for (int nt = 0; nt < 4; nt++) {
            int p = nt * 8 + (lane & 3) * 2;
            *(float2*)(o0 + p) = make_float2(acc[mt][nt][0], acc[mt][nt][1]);
            *(float2*)(o1 + p) = make_float2(acc[mt][nt][2], acc[mt][nt][3]);
        }
    }
}

// ---------------------------------------------------------------------------
extern "C" void kernel_launch(void* const* d_in, const int* in_sizes, int n_in,
                              void* d_out, int out_size) {
    const float* input  = (const float*)d_in[0];
    const float* memory = (const float*)d_in[1];
    const float* wq = (const float*)d_in[2];
    const float* bq = (const float*)d_in[3];
    const float* wk = (const float*)d_in[4];
    const float* bk = (const float*)d_in[5];
    const float* wv = (const float*)d_in[6];
    const float* bv = (const float*)d_in[7];
    float* out = (float*)d_out;

    cudaFuncSetAttribute(convmma_k<3>, cudaFuncAttributeMaxDynamicSharedMemorySize,
                         SMEMSZ);
    cudaFuncSetAttribute(convmma_k<2>, cudaFuncAttributeMaxDynamicSharedMemorySize,
                         SMEMSZ);
    cudaFuncSetAttribute(logits2_k, cudaFuncAttributeMaxDynamicSharedMemorySize,
                         LSMEMSZ);
    cudaFuncSetAttribute(out2_k, cudaFuncAttributeMaxDynamicSharedMemorySize,
                         OSMEM);

    pack_k<<<dim3(BB * LL, 16), 256>>>(input, 0);
    pack_k<<<dim3(BB * LL, 16), 256>>>(memory, 1);
    wprep_k<<<(9 * 8192 + 255) / 256, 256>>>(wq, 9, 0);
    wprep_k<<<(9 * 8192 + 255) / 256, 256>>>(wk, 9, 1);
    wprep_k<<<(27 * 8192 + 255) / 256, 256>>>(wv, 27, 2);

    convmma_k<3><<<dim3(4, BB * LL), 256, SMEMSZ>>>(bq, 0, LL, 9, 0, 0.5f);
    convmma_k<3><<<dim3(4, BB * LL), 256, SMEMSZ>>>(bk, 1, LL, 9, 0, 1.0f);
    convmma_k<2><<<dim3(4, BB * LV), 256, SMEMSZ>>>(bv, 2, LV, 27, 1, 1.0f);

    logits2_k<<<dim3(9, 16), 256, LSMEMSZ>>>();
    softmax_k<<<256, 256>>>();
    out2_k<<<dim3(128, 8), 256, OSMEM>>>(out);
}

// round 7
// speedup vs baseline: 1.2149x; 1.2149x over previous
#include <cuda_runtime.h>
#include <cuda_fp16.h>
#include <cstdint>

#define BB   8
#define CIN  64
#define CO   128
#define LL   18
#define LV   16
#define HW   1024
#define NH   2

// ---------------- scratch (device globals; no allocation allowed) ----------
__device__ float g_lp[(size_t)9*BB*NH*CO*CO];

__device__ __half g_Qh[(size_t)BB*CO*LL*HW];
__device__ __half g_Ql[(size_t)BB*CO*LL*HW];
__device__ __half g_Kh[(size_t)BB*CO*LL*HW];
__device__ __half g_Kl[(size_t)BB*CO*LL*HW];
__device__ __half g_Vh[(size_t)BB*CO*LV*HW];
__device__ __half g_Vl[(size_t)BB*CO*LV*HW];
__device__ __half g_aH[(size_t)BB*NH*CO*CO];
__device__ __half g_aL[(size_t)BB*NH*CO*CO];

__device__ __half g_hin[(size_t)BB*LL*HW*CIN];
__device__ __half g_lin[(size_t)BB*LL*HW*CIN];
__device__ __half g_hmm[(size_t)BB*LL*HW*CIN];
__device__ __half g_lmm[(size_t)BB*LL*HW*CIN];
__device__ uint4 g_wqh[9*1152],  g_wql[9*1152];
__device__ uint4 g_wkh[9*1152],  g_wkl[9*1152];
__device__ uint4 g_wvh[27*1152], g_wvl[27*1152];

// ---------------- PTX helpers ----------------------------------------------
__device__ __forceinline__ uint32_t smem_u32(const void* p) {
    uint32_t a;
    asm("{ .reg .u64 t; cvta.to.shared.u64 t, %1; cvt.u32.u64 %0, t; }"
        : "=r"(a) : "l"(p));
    return a;
}
__device__ __forceinline__ void ldmat4(uint32_t& r0, uint32_t& r1, uint32_t& r2,
                                       uint32_t& r3, uint32_t a) {
    asm volatile("ldmatrix.sync.aligned.m8n8.x4.shared.b16 {%0,%1,%2,%3}, [%4];"
                 : "=r"(r0), "=r"(r1), "=r"(r2), "=r"(r3) : "r"(a));
}
__device__ __forceinline__ void ldmat2t(uint32_t& r0, uint32_t& r1, uint32_t a) {
    asm volatile("ldmatrix.sync.aligned.m8n8.x2.trans.shared.b16 {%0,%1}, [%2];"
                 : "=r"(r0), "=r"(r1) : "r"(a));
}
__device__ __forceinline__ void mma16816(float* c, const uint32_t* a,
                                         const uint32_t* b) {
    asm volatile(
        "mma.sync.aligned.m16n8k16.row.col.f32.f16.f16.f32 "
        "{%0,%1,%2,%3}, {%4,%5,%6,%7}, {%8,%9}, {%0,%1,%2,%3};"
        : "+f"(c[0]), "+f"(c[1]), "+f"(c[2]), "+f"(c[3])
        : "r"(a[0]), "r"(a[1]), "r"(a[2]), "r"(a[3]), "r"(b[0]), "r"(b[1]));
}
__device__ __forceinline__ void cpasync16(uint32_t dst, const void* src, int sz) {
    asm volatile("cp.async.ca.shared.global [%0], [%1], 16, %2;"
                 :: "r"(dst), "l"(src), "r"(sz) : "memory");
}
__device__ __forceinline__ void cp_commit() {
    asm volatile("cp.async.commit_group;" ::: "memory");
}
__device__ __forceinline__ void cp_wait1() {
    asm volatile("cp.async.wait_group 1;" ::: "memory");
}
__device__ __forceinline__ void cp_wait0() {
    asm volatile("cp.async.wait_group 0;" ::: "memory");
}

__device__ __forceinline__ void emit_split(__half* ph, __half* pl,
                                           float x, float y) {
    __half2 h, l;
    h.x = __float2half_rn(x);
    h.y = __float2half_rn(y);
    l.x = __float2half_rn(x - __half2float(h.x));
    l.y = __float2half_rn(y - __half2float(h.y));
    *(__half2*)ph = h;
    *(__half2*)pl = l;
}

// ---------------- prep kernels ---------------------------------------------
__global__ __launch_bounds__(256) void pack_k(const float* __restrict__ x, int dst) {
    __shared__ float tile[64][65];
    const int s = blockIdx.x;
    const int hw0 = blockIdx.y * 64;
    const int b = s / LL, l = s % LL;
    __half* oh = dst ? g_hmm : g_hin;
    __half* ol = dst ? g_lmm : g_lin;
#pragma unroll
    for (int i = 0; i < 16; i++) {
        int idx = threadIdx.x + i * 256;
        int ci = idx >> 6, hw = idx & 63;
        tile[ci][hw] = x[(((size_t)b * CIN + ci) * LL + l) * HW + hw0 + hw];
    }
    __syncthreads();
#pragma unroll
    for (int i = 0; i < 16; i++) {
        int idx = threadIdx.x + i * 256;
        int hw = idx >> 6, ci = idx & 63;
        float v = tile[ci][hw];
        __half h = __float2half_rn(v);
        size_t o = ((size_t)s * HW + hw0 + hw) * CIN + ci;
        oh[o] = h;
        ol[o] = __float2half_rn(v - __half2float(h));
    }
}

__global__ __launch_bounds__(256) void wprep_k(const float* __restrict__ w,
                                               int nchunk, int dst) {
    int i = blockIdx.x * 256 + threadIdx.x;
    if (i >= nchunk * 8192) return;
    int c = i >> 13, r = i & 8191, co = r >> 6, ci = r & 63;
    float v = w[(co * 64 + ci) * nchunk + c];
    __half h = __float2half_rn(v);
    __half lo = __float2half_rn(v - __half2float(h));
    __half *oh, *ol;
    if (dst == 0)      { oh = (__half*)g_wqh; ol = (__half*)g_wql; }
    else if (dst == 1) { oh = (__half*)g_wkh; ol = (__half*)g_wkl; }
    else               { oh = (__half*)g_wvh; ol = (__half*)g_wvl; }
    oh[(size_t)c * 9216 + co * 72 + ci] = h;
    ol[(size_t)c * 9216 + co * 72 + ci] = lo;
}

// ---------------- HMMA implicit-GEMM conv, 128co x 128px, 3-stage ----------
#define ABYTES 18432
#define BUFSZ  73728
#define SMEMSZ (3*BUFSZ)

template<int NPASS>
__device__ __forceinline__ void issue_chunk(
    int c, int is3d, int p0, int b, int l, uint32_t sb,
    const uint4* wh, const uint4* wl,
    const __half* xh, const __half* xl, int tid) {
    int kd, kh, kw;
    if (is3d) { kd = c / 9; int r = c % 9; kh = r / 3; kw = r % 3; }
    else      { kd = 0; kh = c / 3; kw = c % 3; }
    const uint32_t base = sb + (c % 3) * BUFSZ;
    const int acop = (NPASS == 3) ? 2304 : 1152;
#pragma unroll
    for (int i = 0; i < 9; i++) {
        int idx = tid + i * 256;
        if (idx < acop) {
            int half_ = idx >= 1152;
            int r = idx - half_ * 1152;
            const uint4* s = (half_ ? wl : wh) + (size_t)c * 1152 + r;
            cpasync16(base + half_ * ABYTES + r * 16, s, 16);
        }
    }
    {
        int row = tid >> 1, sub = tid & 1;
        int pg = p0 + row;
        int ih = (pg >> 5) + kh - 1, iw = (pg & 31) + kw - 1;
        int ok = ((unsigned)ih < 32u) && ((unsigned)iw < 32u);
        int ihc = ok ? ih : 0, iwc = ok ? iw : 0;
        const __half* s = (sub ? xl : xh) +
            ((size_t)((b * LL + l + kd) * HW) + ihc * 32 + iwc) * CIN;
        uint32_t dst = base + 36864 + sub * ABYTES + row * 144;
        int sz = ok ? 16 : 0;
#pragma unroll
        for (int j = 0; j < 8; j++)
            cpasync16(dst + j * 16, (const char*)s + j * 16, sz);
    }
    cp_commit();
}

template<int NPASS>
__global__ __launch_bounds__(256, 1)
void convmma_k(const float* __restrict__ bias, int mode, int DOUT, int NC,
               int is3d, float scale) {
    extern __shared__ char smem[];
    const uint32_t sb = smem_u32(smem);
    const int tid = threadIdx.x, wid = tid >> 5, lane = tid & 31;
    const int p0 = blockIdx.x * 128;
    const int b = blockIdx.y / DOUT, l = blockIdx.y % DOUT;

    const __half *xh, *xl;
    const uint4 *wh, *wl;
    __half *oph, *opl;
    if (mode == 0)      { xh = g_hin; xl = g_lin; wh = g_wqh; wl = g_wql;
                          oph = g_Qh; opl = g_Ql; }
    else if (mode == 1) { xh = g_hmm; xl = g_lmm; wh = g_wkh; wl = g_wkl;
                          oph = g_Kh; opl = g_Kl; }
    else                { xh = g_hmm; xl = g_lmm; wh = g_wvh; wl = g_wvl;
                          oph = g_Vh; opl = g_Vl; }

    const int co0 = (wid & 1) * 64;
    const int p0l = (wid >> 1) * 32;

    float acc[4][4][4];
#pragma unroll
    for (int mt = 0; mt < 4; mt++)
#pragma unroll
        for (int nt = 0; nt < 4; nt++)
#pragma unroll
            for (int i = 0; i < 4; i++) acc[mt][nt][i] = 0.f;

    issue_chunk<NPASS>(0, is3d, p0, b, l, sb, wh, wl, xh, xl, tid);
    issue_chunk<NPASS>(1, is3d, p0, b, l, sb, wh, wl, xh, xl, tid);

    // B-frag x4 address: lane group -> (nt pair half, k half)
    const int bnt = (lane >> 4) & 1;        // n-tile within pair
    const int bkh = (lane >> 3) & 1;        // k half

    for (int c = 0; c < NC; c++) {
        if (c + 1 < NC) cp_wait1(); else cp_wait0();
        __syncthreads();
        const uint32_t base = sb + (c % 3) * BUFSZ;
        const uint32_t aAh = base, aAl = base + ABYTES;
        const uint32_t aBh = base + 36864, aBl = base + 36864 + ABYTES;
#pragma unroll
        for (int k = 0; k < 4; k++) {
            uint32_t ah[4][4], al[4][4], bh[4][2], bl[4][2];
#pragma unroll
            for (int mt = 0; mt < 4; mt++) {
                uint32_t off = (uint32_t)(((co0 + mt * 16 + (lane & 15)) * 72 +
                                           k * 16 + (lane >> 4) * 8) * 2);
                ldmat4(ah[mt][0], ah[mt][1], ah[mt][2], ah[mt][3], aAh + off);
                if (NPASS == 3)
                    ldmat4(al[mt][0], al[mt][1], al[mt][2], al[mt][3], aAl + off);
            }
#pragma unroll
            for (int pr = 0; pr < 2; pr++) {
                uint32_t off = (uint32_t)(((p0l + (pr * 2 + bnt) * 8 + (lane & 7)) * 72 +
                                           k * 16 + bkh * 8) * 2);
                ldmat4(bh[pr * 2][0], bh[pr * 2][1],
                       bh[pr * 2 + 1][0], bh[pr * 2 + 1][1], aBh + off);
                ldmat4(bl[pr * 2][0], bl[pr * 2][1],
                       bl[pr * 2 + 1][0], bl[pr * 2 + 1][1], aBl + off);
            }
#pragma unroll
            for (int mt = 0; mt < 4; mt++)
#pragma unroll
                for (int nt = 0; nt < 4; nt++)
                    mma16816(acc[mt][nt], ah[mt], bh[nt]);
#pragma unroll
            for (int mt = 0; mt < 4; mt++)
#pragma unroll
                for (int nt = 0; nt < 4; nt++)
                    mma16816(acc[mt][nt], ah[mt], bl[nt]);
            if (NPASS == 3) {
#pragma unroll
                for (int mt = 0; mt < 4; mt++)
#pragma unroll
                    for (int nt = 0; nt < 4; nt++)
                        mma16816(acc[mt][nt], al[mt], bh[nt]);
            }
        }
        if (c + 2 < NC)
            issue_chunk<NPASS>(c + 2, is3d, p0, b, l, sb, wh, wl, xh, xl, tid);
    }

#pragma unroll
    for (int mt = 0; mt < 4; mt++) {
        int co = co0 + mt * 16 + (lane >> 2);
        float bv0 = bias[co];
        float bv1 = bias[co + 8];
        size_t o0 = ((size_t)(b * CO + co) * DOUT + l) * HW + p0 + p0l;
        size_t o1 = o0 + (size_t)8 * DOUT * HW;
#pragma unroll
        for (int nt = 0; nt < 4; nt++) {
            int p = nt * 8 + (lane & 3) * 2;
            emit_split(oph + o0 + p, opl + o0 + p,
                       (acc[mt][nt][0] + bv0) * scale,
                       (acc[mt][nt][1] + bv0) * scale);
            emit_split(oph + o1 + p, opl + o1 + p,
                       (acc[mt][nt][2] + bv1) * scale,
                       (acc[mt][nt][3] + bv1) * scale);
        }
    }
}

// ---------------- logits: Q.K^T via HMMA, split-K over 9 l-slices ----------
#define LSMEMSZ (2*BUFSZ)

__global__ __launch_bounds__(256, 1) void logits2_k() {
    extern __shared__ char smem[];
    const uint32_t sb = smem_u32(smem);
    const int tid = threadIdx.x, wid = tid >> 5, lane = tid & 31;
    const int lc = blockIdx.x, bn = blockIdx.y;
    const int b = bn >> 1, n = bn & 1;
    const int l = n * 9 + lc;

    const __half* srcs[4];
    srcs[0] = g_Qh + ((size_t)(b * CO) * LL + l) * HW;
    srcs[1] = g_Ql + ((size_t)(b * CO) * LL + l) * HW;
    srcs[2] = g_Kh + ((size_t)(b * CO) * LL + l) * HW;
    srcs[3] = g_Kl + ((size_t)(b * CO) * LL + l) * HW;

    const int co0 = (wid & 1) * 64;
    const int p0l = (wid >> 1) * 32;
    const int bnt = (lane >> 4) & 1;
    const int bkh = (lane >> 3) & 1;

    float acc[4][4][4];
#pragma unroll
    for (int mt = 0; mt < 4; mt++)
#pragma unroll
        for (int nt = 0; nt < 4; nt++)
#pragma unroll
            for (int i = 0; i < 4; i++) acc[mt][nt][i] = 0.f;

    auto issue = [&](int ch) {
        const uint32_t base = sb + (ch & 1) * BUFSZ;
        const int hw0 = ch * 64;
#pragma unroll
        for (int r = tid; r < 512; r += 256) {
            int plane = r >> 7, c = r & 127;
            const __half* s = srcs[plane] + (size_t)c * (LL * HW) + hw0;
            uint32_t dst = base + plane * ABYTES + c * 144;
#pragma unroll
            for (int j = 0; j < 8; j++)
                cpasync16(dst + j * 16, (const char*)s + j * 16, 16);
        }
        cp_commit();
    };

    issue(0);
    for (int ch = 0; ch < 16; ch++) {
        if (ch + 1 < 16) { issue(ch + 1); cp_wait1(); }
        else             { cp_wait0(); }
        __syncthreads();
        const uint32_t base = sb + (ch & 1) * BUFSZ;
        const uint32_t aAh = base, aAl = base + ABYTES;
        const uint32_t aBh = base + 2 * ABYTES, aBl = base + 3 * ABYTES;
#pragma unroll
        for (int k = 0; k < 4; k++) {
            uint32_t ah[4][4], al[4][4], bh[4][2], bl[4][2];
#pragma unroll
            for (int mt = 0; mt < 4; mt++) {
                uint32_t off = (uint32_t)(((co0 + mt * 16 + (lane & 15)) * 72 +
                                           k * 16 + (lane >> 4) * 8) * 2);
                ldmat4(ah[mt][0], ah[mt][1], ah[mt][2], ah[mt][3], aAh + off);
                ldmat4(al[mt][0], al[mt][1], al[mt][2], al[mt][3], aAl + off);
            }
#pragma unroll
            for (int pr = 0; pr < 2; pr++) {
                uint32_t off = (uint32_t)(((p0l + (pr * 2 + bnt) * 8 + (lane & 7)) * 72 +
                                           k * 16 + bkh * 8) * 2);
                ldmat4(bh[pr * 2][0], bh[pr * 2][1],
                       bh[pr * 2 + 1][0], bh[pr * 2 + 1][1], aBh + off);
                ldmat4(bl[pr * 2][0], bl[pr * 2][1],
                       bl[pr * 2 + 1][0], bl[pr * 2 + 1][1], aBl + off);
            }
#pragma unroll
            for (int mt = 0; mt < 4; mt++)
#pragma unroll
                for (int nt = 0; nt < 4; nt++)
                    mma16816(acc[mt][nt], ah[mt], bh[nt]);
#pragma unroll
            for (int mt = 0; mt < 4; mt++)
#pragma unroll
                for (int nt = 0; nt < 4; nt++)
                    mma16816(acc[mt][nt], ah[mt], bl[nt]);
#pragma unroll
            for (int mt = 0; mt < 4; mt++)
#pragma unroll
                for (int nt = 0; nt < 4; nt++)
                    mma16816(acc[mt][nt], al[mt], bh[nt]);
        }
        __syncthreads();
    }

    float* lp = g_lp + ((size_t)lc * 16 + bn) * CO * CO;
#pragma unroll
    for (int mt = 0; mt < 4; mt++) {
        int c = co0 + mt * 16 + (lane >> 2);
#pragma unroll
        for (int nt = 0; nt < 4; nt++) {
            int m = p0l + nt * 8 + (lane & 3) * 2;
            *(float2*)(lp + (size_t)c * CO + m) =
                make_float2(acc[mt][nt][0], acc[mt][nt][1]);
            *(float2*)(lp + (size_t)(c + 8) * CO + m) =
                make_float2(acc[mt][nt][2], acc[mt][nt][3]);
        }
    }
}

// ---------------- softmax ---------------------------------------------------
__global__ __launch_bounds__(256) void softmax_k() {
    const int warp = (blockIdx.x * 256 + threadIdx.x) >> 5;
    const int lane = threadIdx.x & 31;
    if (warp >= 16 * CO) return;
    const int bn = warp >> 7, c = warp & 127;
    float v[4];
#pragma unroll
    for (int j = 0; j < 4; j++) {
        int m = lane + j * 32;
        float s = 0.f;
#pragma unroll
        for (int p = 0; p < 9; p++)
            s += g_lp[(((size_t)p * 16 + bn) * CO + c) * CO + m];
        v[j] = s;
    }
    float mx = fmaxf(fmaxf(v[0], v[1]), fmaxf(v[2], v[3]));
#pragma unroll
    for (int o = 16; o; o >>= 1) mx = fmaxf(mx, __shfl_xor_sync(0xffffffffu, mx, o));
    float sum = 0.f;
#pragma unroll
    for (int j = 0; j < 4; j++) { v[j] = __expf(v[j] - mx); sum += v[j]; }
#pragma unroll
    for (int o = 16; o; o >>= 1) sum += __shfl_xor_sync(0xffffffffu, sum, o);
    float inv = 1.f / sum;
#pragma unroll
    for (int j = 0; j < 4; j++) {
        float a = v[j] * inv;
        __half h = __float2half_rn(a);
        size_t o = ((size_t)bn * CO + c) * CO + lane + j * 32;
        g_aH[o] = h;
        g_aL[o] = __float2half_rn(a - __half2float(h));
    }
}

// ---------------- out: attn x V via HMMA -----------------------------------
#define OPITCH 272
#define OTILE  34816
#define OSMEM  (4*OTILE)

__global__ __launch_bounds__(256, 1) void out2_k(float* __restrict__ out) {
    extern __shared__ char smem[];
    const uint32_t sb = smem_u32(smem);
    const int tid = threadIdx.x, wid = tid >> 5, lane = tid & 31;
    const int pt = blockIdx.x, b = blockIdx.y;
    const int l = pt >> 3;
    const int hw0 = (pt & 7) * 128;
    const int bn = b * 2 + (l >> 3);

    {
        int plane = tid >> 7, c = tid & 127;
        const __half* s =
            (plane ? g_aL : g_aH) + ((size_t)bn * CO + c) * CO;
        uint32_t dst = sb + plane * OTILE + c * OPITCH;
#pragma unroll
        for (int j = 0; j < 16; j++)
            cpasync16(dst + j * 16, (const char*)s + j * 16, 16);
        const __half* sv =
            (plane ? g_Vl : g_Vh) + ((size_t)(b * CO + c) * LV + l) * HW + hw0;
        uint32_t dv = sb + 2 * OTILE + plane * OTILE + c * OPITCH;
#pragma unroll
        for (int j = 0; j < 16; j++)
            cpasync16(dv + j * 16, (const char*)sv + j * 16, 16);
    }
    cp_commit();
    cp_wait0();
    __syncthreads();

    const int co0 = (wid & 1) * 64;
    const int p0l = (wid >> 1) * 32;
    const uint32_t aAh = sb, aAl = sb + OTILE;
    const uint32_t aBh = sb + 2 * OTILE, aBl = sb + 3 * OTILE;

    float acc[4][4][4];
#pragma unroll
    for (int mt = 0; mt < 4; mt++)
#pragma unroll
        for (int nt = 0; nt < 4; nt++)
#pragma unroll
            for (int i = 0; i < 4; i++) acc[mt][nt][i] = 0.f;

#pragma unroll
    for (int kc = 0; kc < 8; kc++) {
        uint32_t ah[4][4], al[4][4], bh[4][2], bl[4][2];
#pragma unroll
        for (int mt = 0; mt < 4; mt++) {
            uint32_t off = (uint32_t)((co0 + mt * 16 + (lane & 15)) * OPITCH +
                                      kc * 32 + (lane >> 4) * 16);
            ldmat4(ah[mt][0], ah[mt][1], ah[mt][2], ah[mt][3], aAh + off);
            ldmat4(al[mt][0], al[mt][1], al[mt][2], al[mt][3], aAl + off);
        }
#pragma unroll
        for (int nt = 0; nt < 4; nt++) {
            uint32_t off = (uint32_t)((kc * 16 + (lane & 15)) * OPITCH +
                                      (p0l + nt * 8) * 2);
            ldmat2t(bh[nt][0], bh[nt][1], aBh + off);
            ldmat2t(bl[nt][0], bl[nt][1], aBl + off);
        }
#pragma unroll
        for (int mt = 0; mt < 4; mt++)
#pragma unroll
            for (int nt = 0; nt < 4; nt++)
                mma16816(acc[mt][nt], ah[mt], bh[nt]);
#pragma unroll
        for (int mt = 0; mt < 4; mt++)
#pragma unroll
            for (int nt = 0; nt < 4; nt++)
                mma16816(acc[mt][nt], ah[mt], bl[nt]);
#pragma unroll
        for (int mt = 0; mt < 4; mt++)
#pragma unroll
            for (int nt = 0; nt < 4; nt++)
                mma16816(acc[mt][nt], al[mt], bh[nt]);
    }

#pragma unroll
    for (int mt = 0; mt < 4; mt++) {
        int c = co0 + mt * 16 + (lane >> 2);
        float* o0 = out + ((size_t)(b * CO + c) * LV + l) * HW + hw0 + p0l;
        float* o1 = o0 + (size_t)8 * LV * HW;
#pragma unroll
        for (int nt = 0; nt < 4; nt++) {
            int p = nt * 8 + (lane & 3) * 2;
            *(float2*)(o0 + p) = make_float2(acc[mt][nt][0], acc[mt][nt][1]);
            *(float2*)(o1 + p) = make_float2(acc[mt][nt][2], acc[mt][nt][3]);
        }
    }
}

// ---------------------------------------------------------------------------
extern "C" void kernel_launch(void* const* d_in, const int* in_sizes, int n_in,
                              void* d_out, int out_size) {
    const float* input  = (const float*)d_in[0];
    const float* memory = (const float*)d_in[1];
    const float* wq = (const float*)d_in[2];
    const float* bq = (const float*)d_in[3];
    const float* wk = (const float*)d_in[4];
    const float* bk = (const float*)d_in[5];
    const float* wv = (const float*)d_in[6];
    const float* bv = (const float*)d_in[7];
    float* out = (float*)d_out;

    cudaFuncSetAttribute(convmma_k<3>, cudaFuncAttributeMaxDynamicSharedMemorySize,
                         SMEMSZ);
    cudaFuncSetAttribute(convmma_k<2>, cudaFuncAttributeMaxDynamicSharedMemorySize,
                         SMEMSZ);
    cudaFuncSetAttribute(logits2_k, cudaFuncAttributeMaxDynamicSharedMemorySize,
                         LSMEMSZ);
    cudaFuncSetAttribute(out2_k, cudaFuncAttributeMaxDynamicSharedMemorySize,
                         OSMEM);

    pack_k<<<dim3(BB * LL, 16), 256>>>(input, 0);
    pack_k<<<dim3(BB * LL, 16), 256>>>(memory, 1);
    wprep_k<<<(9 * 8192 + 255) / 256, 256>>>(wq, 9, 0);
    wprep_k<<<(9 * 8192 + 255) / 256, 256>>>(wk, 9, 1);
    wprep_k<<<(27 * 8192 + 255) / 256, 256>>>(wv, 27, 2);

    convmma_k<3><<<dim3(8, BB * LL), 256, SMEMSZ>>>(bq, 0, LL, 9, 0, 0.5f);
    convmma_k<3><<<dim3(8, BB * LL), 256, SMEMSZ>>>(bk, 1, LL, 9, 0, 1.0f);
    convmma_k<2><<<dim3(8, BB * LV), 256, SMEMSZ>>>(bv, 2, LV, 27, 1, 1.0f);

    logits2_k<<<dim3(9, 16), 256, LSMEMSZ>>>();
    softmax_k<<<256, 256>>>();
    out2_k<<<dim3(128, 8), 256, OSMEM>>>(out);
}

// round 8
// speedup vs baseline: 1.5143x; 1.2464x over previous
#include <cuda_runtime.h>
#include <cuda_fp16.h>
#include <cstdint>

#define BB   8
#define CIN  64
#define CO   128
#define LL   18
#define LV   16
#define HW   1024
#define NH   2

// ---------------- scratch (device globals; no allocation allowed) ----------
__device__ float g_lp[(size_t)9*BB*NH*CO*CO];

__device__ __half g_Qh[(size_t)BB*CO*LL*HW];
__device__ __half g_Ql[(size_t)BB*CO*LL*HW];
__device__ __half g_Kh[(size_t)BB*CO*LL*HW];
__device__ __half g_Kl[(size_t)BB*CO*LL*HW];
__device__ __half g_Vh[(size_t)BB*CO*LV*HW];
__device__ __half g_aH[(size_t)BB*NH*CO*CO];
__device__ __half g_aL[(size_t)BB*NH*CO*CO];

__device__ __half g_hin[(size_t)BB*LL*HW*CIN];
__device__ __half g_lin[(size_t)BB*LL*HW*CIN];
__device__ __half g_hmm[(size_t)BB*LL*HW*CIN];
__device__ __half g_lmm[(size_t)BB*LL*HW*CIN];
__device__ uint4 g_wqh[9*1152],  g_wql[9*1152];
__device__ uint4 g_wkh[9*1152],  g_wkl[9*1152];
__device__ uint4 g_wvh[27*1152], g_wvl[27*1152];

// ---------------- PTX helpers ----------------------------------------------
__device__ __forceinline__ uint32_t smem_u32(const void* p) {
    uint32_t a;
    asm("{ .reg .u64 t; cvta.to.shared.u64 t, %1; cvt.u32.u64 %0, t; }"
        : "=r"(a) : "l"(p));
    return a;
}
__device__ __forceinline__ void ldmat4(uint32_t& r0, uint32_t& r1, uint32_t& r2,
                                       uint32_t& r3, uint32_t a) {
    asm volatile("ldmatrix.sync.aligned.m8n8.x4.shared.b16 {%0,%1,%2,%3}, [%4];"
                 : "=r"(r0), "=r"(r1), "=r"(r2), "=r"(r3) : "r"(a));
}
__device__ __forceinline__ void ldmat2t(uint32_t& r0, uint32_t& r1, uint32_t a) {
    asm volatile("ldmatrix.sync.aligned.m8n8.x2.trans.shared.b16 {%0,%1}, [%2];"
                 : "=r"(r0), "=r"(r1) : "r"(a));
}
__device__ __forceinline__ void mma16816(float* c, const uint32_t* a,
                                         const uint32_t* b) {
    asm volatile(
        "mma.sync.aligned.m16n8k16.row.col.f32.f16.f16.f32 "
        "{%0,%1,%2,%3}, {%4,%5,%6,%7}, {%8,%9}, {%0,%1,%2,%3};"
        : "+f"(c[0]), "+f"(c[1]), "+f"(c[2]), "+f"(c[3])
        : "r"(a[0]), "r"(a[1]), "r"(a[2]), "r"(a[3]), "r"(b[0]), "r"(b[1]));
}
__device__ __forceinline__ void cpasync16(uint32_t dst, const void* src, int sz) {
    asm volatile("cp.async.ca.shared.global [%0], [%1], 16, %2;"
                 :: "r"(dst), "l"(src), "r"(sz) : "memory");
}
__device__ __forceinline__ void cp_commit() {
    asm volatile("cp.async.commit_group;" ::: "memory");
}
__device__ __forceinline__ void cp_wait1() {
    asm volatile("cp.async.wait_group 1;" ::: "memory");
}
__device__ __forceinline__ void cp_wait0() {
    asm volatile("cp.async.wait_group 0;" ::: "memory");
}

__device__ __forceinline__ void emit_split(__half* ph, __half* pl,
                                           float x, float y) {
    __half2 h, l;
    h.x = __float2half_rn(x);
    h.y = __float2half_rn(y);
    l.x = __float2half_rn(x - __half2float(h.x));
    l.y = __float2half_rn(y - __half2float(h.y));
    *(__half2*)ph = h;
    *(__half2*)pl = l;
}

// ---------------- prep kernels ---------------------------------------------
__global__ __launch_bounds__(256) void pack_k(const float* __restrict__ x0,
                                              const float* __restrict__ x1) {
    __shared__ float tile[64][65];
    const int s = blockIdx.x;
    const int hw0 = blockIdx.y * 64;
    const int dst = blockIdx.z;
    const int b = s / LL, l = s % LL;
    const float* x = dst ? x1 : x0;
    __half* oh = dst ? g_hmm : g_hin;
    __half* ol = dst ? g_lmm : g_lin;
#pragma unroll
    for (int i = 0; i < 16; i++) {
        int idx = threadIdx.x + i * 256;
        int ci = idx >> 6, hw = idx & 63;
        tile[ci][hw] = x[(((size_t)b * CIN + ci) * LL + l) * HW + hw0 + hw];
    }
    __syncthreads();
#pragma unroll
    for (int i = 0; i < 16; i++) {
        int idx = threadIdx.x + i * 256;
        int hw = idx >> 6, ci = idx & 63;
        float v = tile[ci][hw];
        __half h = __float2half_rn(v);
        size_t o = ((size_t)s * HW + hw0 + hw) * CIN + ci;
        oh[o] = h;
        ol[o] = __float2half_rn(v - __half2float(h));
    }
}

// all three weight preps in one launch: idx space [0, 45*8192)
__global__ __launch_bounds__(256) void wprep_k(const float* __restrict__ wq,
                                               const float* __restrict__ wk,
                                               const float* __restrict__ wv) {
    int i = blockIdx.x * 256 + threadIdx.x;
    if (i >= 45 * 8192) return;
    const float* w;
    __half *oh, *ol;
    int nchunk;
    if (i < 9 * 8192)        { w = wq; oh = (__half*)g_wqh; ol = (__half*)g_wql;
                               nchunk = 9; }
    else if (i < 18 * 8192)  { w = wk; oh = (__half*)g_wkh; ol = (__half*)g_wkl;
                               nchunk = 9; i -= 9 * 8192; }
    else                     { w = wv; oh = (__half*)g_wvh; ol = (__half*)g_wvl;
                               nchunk = 27; i -= 18 * 8192; }
    int c = i >> 13, r = i & 8191, co = r >> 6, ci = r & 63;
    float v = w[(co * 64 + ci) * nchunk + c];
    __half h = __float2half_rn(v);
    __half lo = __float2half_rn(v - __half2float(h));
    oh[(size_t)c * 9216 + co * 72 + ci] = h;
    ol[(size_t)c * 9216 + co * 72 + ci] = lo;
}

// ---------------- HMMA implicit-GEMM conv, 128co x 128px, 3-stage ----------
#define ABYTES 18432
#define BUFSZ  73728
#define SMEMSZ (3*BUFSZ)

template<int NPASS>
__device__ __forceinline__ void issue_chunk(
    int c, int is3d, int p0, int b, int l, uint32_t sb,
    const uint4* wh, const uint4* wl,
    const __half* xh, const __half* xl, int tid) {
    int kd, kh, kw;
    if (is3d) { kd = c / 9; int r = c % 9; kh = r / 3; kw = r % 3; }
    else      { kd = 0; kh = c / 3; kw = c % 3; }
    const uint32_t base = sb + (c % 3) * BUFSZ;
    const int acop = (NPASS == 3) ? 2304 : 1152;
#pragma unroll
    for (int i = 0; i < 9; i++) {
        int idx = tid + i * 256;
        if (idx < acop) {
            int half_ = idx >= 1152;
            int r = idx - half_ * 1152;
            const uint4* s = (half_ ? wl : wh) + (size_t)c * 1152 + r;
            cpasync16(base + half_ * ABYTES + r * 16, s, 16);
        }
    }
    if (NPASS > 1 || tid < 128) {
        int row, sub;
        if (NPASS > 1) { row = tid >> 1; sub = tid & 1; }
        else           { row = tid;      sub = 0; }
        int pg = p0 + row;
        int ih = (pg >> 5) + kh - 1, iw = (pg & 31) + kw - 1;
        int ok = ((unsigned)ih < 32u) && ((unsigned)iw < 32u);
        int ihc = ok ? ih : 0, iwc = ok ? iw : 0;
        const __half* s = (sub ? xl : xh) +
            ((size_t)((b * LL + l + kd) * HW) + ihc * 32 + iwc) * CIN;
        uint32_t dst = base + 36864 + sub * ABYTES + row * 144;
        int sz = ok ? 16 : 0;
#pragma unroll
        for (int j = 0; j < 8; j++)
            cpasync16(dst + j * 16, (const char*)s + j * 16, sz);
    }
    cp_commit();
}

template<int NPASS>
__global__ __launch_bounds__(256, 1)
void convmma_k(const float* __restrict__ bias, int mode, int DOUT, int NC,
               int is3d, float scale) {
    extern __shared__ char smem[];
    const uint32_t sb = smem_u32(smem);
    const int tid = threadIdx.x, wid = tid >> 5, lane = tid & 31;
    const int p0 = blockIdx.x * 128;
    const int b = blockIdx.y / DOUT, l = blockIdx.y % DOUT;

    const __half *xh, *xl;
    const uint4 *wh, *wl;
    __half *oph, *opl;
    if (mode == 0)      { xh = g_hin; xl = g_lin; wh = g_wqh; wl = g_wql;
                          oph = g_Qh; opl = g_Ql; }
    else if (mode == 1) { xh = g_hmm; xl = g_lmm; wh = g_wkh; wl = g_wkl;
                          oph = g_Kh; opl = g_Kl; }
    else                { xh = g_hmm; xl = g_lmm; wh = g_wvh; wl = g_wvl;
                          oph = g_Vh; opl = g_Vh; }

    const int co0 = (wid & 1) * 64;
    const int p0l = (wid >> 1) * 32;

    float acc[4][4][4];
#pragma unroll
    for (int mt = 0; mt < 4; mt++)
#pragma unroll
        for (int nt = 0; nt < 4; nt++)
#pragma unroll
            for (int i = 0; i < 4; i++) acc[mt][nt][i] = 0.f;

    issue_chunk<NPASS>(0, is3d, p0, b, l, sb, wh, wl, xh, xl, tid);
    issue_chunk<NPASS>(1, is3d, p0, b, l, sb, wh, wl, xh, xl, tid);

    const int bnt = (lane >> 4) & 1;
    const int bkh = (lane >> 3) & 1;

    for (int c = 0; c < NC; c++) {
        if (c + 1 < NC) cp_wait1(); else cp_wait0();
        __syncthreads();
        const uint32_t base = sb + (c % 3) * BUFSZ;
        const uint32_t aAh = base, aAl = base + ABYTES;
        const uint32_t aBh = base + 36864, aBl = base + 36864 + ABYTES;
#pragma unroll
        for (int k = 0; k < 4; k++) {
            uint32_t ah[4][4], al[4][4], bh[4][2], bl[4][2];
#pragma unroll
            for (int mt = 0; mt < 4; mt++) {
                uint32_t off = (uint32_t)(((co0 + mt * 16 + (lane & 15)) * 72 +
                                           k * 16 + (lane >> 4) * 8) * 2);
                ldmat4(ah[mt][0], ah[mt][1], ah[mt][2], ah[mt][3], aAh + off);
                if (NPASS == 3)
                    ldmat4(al[mt][0], al[mt][1], al[mt][2], al[mt][3], aAl + off);
            }
#pragma unroll
            for (int pr = 0; pr < 2; pr++) {
                uint32_t off = (uint32_t)(((p0l + (pr * 2 + bnt) * 8 + (lane & 7)) * 72 +
                                           k * 16 + bkh * 8) * 2);
                ldmat4(bh[pr * 2][0], bh[pr * 2][1],
                       bh[pr * 2 + 1][0], bh[pr * 2 + 1][1], aBh + off);
                if (NPASS >= 2)
                    ldmat4(bl[pr * 2][0], bl[pr * 2][1],
                           bl[pr * 2 + 1][0], bl[pr * 2 + 1][1], aBl + off);
            }
#pragma unroll
            for (int mt = 0; mt < 4; mt++)
#pragma unroll
                for (int nt = 0; nt < 4; nt++)
                    mma16816(acc[mt][nt], ah[mt], bh[nt]);
            if (NPASS >= 2) {
#pragma unroll
                for (int mt = 0; mt < 4; mt++)
#pragma unroll
                    for (int nt = 0; nt < 4; nt++)
                        mma16816(acc[mt][nt], ah[mt], bl[nt]);
            }
            if (NPASS == 3) {
#pragma unroll
                for (int mt = 0; mt < 4; mt++)
#pragma unroll
                    for (int nt = 0; nt < 4; nt++)
                        mma16816(acc[mt][nt], al[mt], bh[nt]);
            }
        }
        if (c + 2 < NC)
            issue_chunk<NPASS>(c + 2, is3d, p0, b, l, sb, wh, wl, xh, xl, tid);
    }

#pragma unroll
    for (int mt = 0; mt < 4; mt++) {
        int co = co0 + mt * 16 + (lane >> 2);
        float bv0 = bias[co];
        float bv1 = bias[co + 8];
        size_t o0 = ((size_t)(b * CO + co) * DOUT + l) * HW + p0 + p0l;
        size_t o1 = o0 + (size_t)8 * DOUT * HW;
#pragma unroll
        for (int nt = 0; nt < 4; nt++) {
            int p = nt * 8 + (lane & 3) * 2;
            if (NPASS == 1) {
                __half2 v0, v1;
                v0.x = __float2half_rn((acc[mt][nt][0] + bv0) * scale);
                v0.y = __float2half_rn((acc[mt][nt][1] + bv0) * scale);
                v1.x = __float2half_rn((acc[mt][nt][2] + bv1) * scale);
                v1.y = __float2half_rn((acc[mt][nt][3] + bv1) * scale);
                *(__half2*)(oph + o0 + p) = v0;
                *(__half2*)(oph + o1 + p) = v1;
            } else {
                emit_split(oph + o0 + p, opl + o0 + p,
                           (acc[mt][nt][0] + bv0) * scale,
                           (acc[mt][nt][1] + bv0) * scale);
                emit_split(oph + o1 + p, opl + o1 + p,
                           (acc[mt][nt][2] + bv1) * scale,
                           (acc[mt][nt][3] + bv1) * scale);
            }
        }
    }
}

// ---------------- logits: Q.K^T via HMMA, split-K over 9 l-slices ----------
#define LSMEMSZ (2*BUFSZ)

__global__ __launch_bounds__(256, 1) void logits2_k() {
    extern __shared__ char smem[];
    const uint32_t sb = smem_u32(smem);
    const int tid = threadIdx.x, wid = tid >> 5, lane = tid & 31;
    const int lc = blockIdx.x, bn = blockIdx.y;
    const int b = bn >> 1, n = bn & 1;
    const int l = n * 9 + lc;

    const __half* srcs[4];
    srcs[0] = g_Qh + ((size_t)(b * CO) * LL + l) * HW;
    srcs[1] = g_Ql + ((size_t)(b * CO) * LL + l) * HW;
    srcs[2] = g_Kh + ((size_t)(b * CO) * LL + l) * HW;
    srcs[3] = g_Kl + ((size_t)(b * CO) * LL + l) * HW;

    const int co0 = (wid & 1) * 64;
    const int p0l = (wid >> 1) * 32;
    const int bnt = (lane >> 4) & 1;
    const int bkh = (lane >> 3) & 1;

    float acc[4][4][4];
#pragma unroll
    for (int mt = 0; mt < 4; mt++)
#pragma unroll
        for (int nt = 0; nt < 4; nt++)
#pragma unroll
            for (int i = 0; i < 4; i++) acc[mt][nt][i] = 0.f;

    auto issue = [&](int ch) {
        const uint32_t base = sb + (ch & 1) * BUFSZ;
        const int hw0 = ch * 64;
#pragma unroll
        for (int r = tid; r < 512; r += 256) {
            int plane = r >> 7, c = r & 127;
            const __half* s = srcs[plane] + (size_t)c * (LL * HW) + hw0;
            uint32_t dst = base + plane * ABYTES + c * 144;
#pragma unroll
            for (int j = 0; j < 8; j++)
                cpasync16(dst + j * 16, (const char*)s + j * 16, 16);
        }
        cp_commit();
    };

    issue(0);
    for (int ch = 0; ch < 16; ch++) {
        if (ch + 1 < 16) { issue(ch + 1); cp_wait1(); }
        else             { cp_wait0(); }
        __syncthreads();
        const uint32_t base = sb + (ch & 1) * BUFSZ;
        const uint32_t aAh = base, aAl = base + ABYTES;
        const uint32_t aBh = base + 2 * ABYTES, aBl = base + 3 * ABYTES;
#pragma unroll
        for (int k = 0; k < 4; k++) {
            uint32_t ah[4][4], al[4][4], bh[4][2], bl[4][2];
#pragma unroll
            for (int mt = 0; mt < 4; mt++) {
                uint32_t off = (uint32_t)(((co0 + mt * 16 + (lane & 15)) * 72 +
                                           k * 16 + (lane >> 4) * 8) * 2);
                ldmat4(ah[mt][0], ah[mt][1], ah[mt][2], ah[mt][3], aAh + off);
                ldmat4(al[mt][0], al[mt][1], al[mt][2], al[mt][3], aAl + off);
            }
#pragma unroll
            for (int pr = 0; pr < 2; pr++) {
                uint32_t off = (uint32_t)(((p0l + (pr * 2 + bnt) * 8 + (lane & 7)) * 72 +
                                           k * 16 + bkh * 8) * 2);
                ldmat4(bh[pr * 2][0], bh[pr * 2][1],
                       bh[pr * 2 + 1][0], bh[pr * 2 + 1][1], aBh + off);
                ldmat4(bl[pr * 2][0], bl[pr * 2][1],
                       bl[pr * 2 + 1][0], bl[pr * 2 + 1][1], aBl + off);
            }
#pragma unroll
            for (int mt = 0; mt < 4; mt++)
#pragma unroll
                for (int nt = 0; nt < 4; nt++)
                    mma16816(acc[mt][nt], ah[mt], bh[nt]);
#pragma unroll
            for (int mt = 0; mt < 4; mt++)
#pragma unroll
                for (int nt = 0; nt < 4; nt++)
                    mma16816(acc[mt][nt], ah[mt], bl[nt]);
#pragma unroll
            for (int mt = 0; mt < 4; mt++)
#pragma unroll
                for (int nt = 0; nt < 4; nt++)
                    mma16816(acc[mt][nt], al[mt], bh[nt]);
        }
        __syncthreads();
    }

    float* lp = g_lp + ((size_t)lc * 16 + bn) * CO * CO;
#pragma unroll
    for (int mt = 0; mt < 4; mt++) {
        int c = co0 + mt * 16 + (lane >> 2);
#pragma unroll
        for (int nt = 0; nt < 4; nt++) {
            int m = p0l + nt * 8 + (lane & 3) * 2;
            *(float2*)(lp + (size_t)c * CO + m) =
                make_float2(acc[mt][nt][0], acc[mt][nt][1]);
            *(float2*)(lp + (size_t)(c + 8) * CO + m) =
                make_float2(acc[mt][nt][2], acc[mt][nt][3]);
        }
    }
}

// ---------------- softmax ---------------------------------------------------
__global__ __launch_bounds__(256) void softmax_k() {
    const int warp = (blockIdx.x * 256 + threadIdx.x) >> 5;
    const int lane = threadIdx.x & 31;
    if (warp >= 16 * CO) return;
    const int bn = warp >> 7, c = warp & 127;
    float v[4];
#pragma unroll
    for (int j = 0; j < 4; j++) {
        int m = lane + j * 32;
        float s = 0.f;
#pragma unroll
        for (int p = 0; p < 9; p++)
            s += g_lp[(((size_t)p * 16 + bn) * CO + c) * CO + m];
        v[j] = s;
    }
    float mx = fmaxf(fmaxf(v[0], v[1]), fmaxf(v[2], v[3]));
#pragma unroll
    for (int o = 16; o; o >>= 1) mx = fmaxf(mx, __shfl_xor_sync(0xffffffffu, mx, o));
    float sum = 0.f;
#pragma unroll
    for (int j = 0; j < 4; j++) { v[j] = __expf(v[j] - mx); sum += v[j]; }
#pragma unroll
    for (int o = 16; o; o >>= 1) sum += __shfl_xor_sync(0xffffffffu, sum, o);
    float inv = 1.f / sum;
#pragma unroll
    for (int j = 0; j < 4; j++) {
        float a = v[j] * inv;
        __half h = __float2half_rn(a);
        size_t o = ((size_t)bn * CO + c) * CO + lane + j * 32;
        g_aH[o] = h;
        g_aL[o] = __float2half_rn(a - __half2float(h));
    }
}

// ---------------- out: attn(hi,lo) x V(fp16) via HMMA, 2 passes ------------
#define OPITCH 272
#define OTILE  34816
#define OSMEM  (3*OTILE)

__global__ __launch_bounds__(256, 1) void out2_k(float* __restrict__ out) {
    extern __shared__ char smem[];
    const uint32_t sb = smem_u32(smem);
    const int tid = threadIdx.x, wid = tid >> 5, lane = tid & 31;
    const int pt = blockIdx.x, b = blockIdx.y;
    const int l = pt >> 3;
    const int hw0 = (pt & 7) * 128;
    const int bn = b * 2 + (l >> 3);

    {
        int c = tid & 127;
        if (tid < 128) {
            const __half* s = g_aH + ((size_t)bn * CO + c) * CO;
            uint32_t dst = sb + c * OPITCH;
#pragma unroll
            for (int j = 0; j < 16; j++)
                cpasync16(dst + j * 16, (const char*)s + j * 16, 16);
            const __half* sv = g_Vh + ((size_t)(b * CO + c) * LV + l) * HW + hw0;
            uint32_t dv = sb + 2 * OTILE + c * OPITCH;
#pragma unroll
            for (int j = 0; j < 16; j++)
                cpasync16(dv + j * 16, (const char*)sv + j * 16, 16);
        } else {
            const __half* s = g_aL + ((size_t)bn * CO + c) * CO;
            uint32_t dst = sb + OTILE + c * OPITCH;
#pragma unroll
            for (int j = 0; j < 16; j++)
                cpasync16(dst + j * 16, (const char*)s + j * 16, 16);
        }
    }
    cp_commit();
    cp_wait0();
    __syncthreads();

    const int co0 = (wid & 1) * 64;
    const int p0l = (wid >> 1) * 32;
    const uint32_t aAh = sb, aAl = sb + OTILE;
    const uint32_t aB = sb + 2 * OTILE;

    float acc[4][4][4];
#pragma unroll
    for (int mt = 0; mt < 4; mt++)
#pragma unroll
        for (int nt = 0; nt < 4; nt++)
#pragma unroll
            for (int i = 0; i < 4; i++) acc[mt][nt][i] = 0.f;

#pragma unroll
    for (int kc = 0; kc < 8; kc++) {
        uint32_t ah[4][4], al[4][4], bh[4][2];
#pragma unroll
        for (int mt = 0; mt < 4; mt++) {
            uint32_t off = (uint32_t)((co0 + mt * 16 + (lane & 15)) * OPITCH +
                                      kc * 32 + (lane >> 4) * 16);
            ldmat4(ah[mt][0], ah[mt][1], ah[mt][2], ah[mt][3], aAh + off);
            ldmat4(al[mt][0], al[mt][1], al[mt][2], al[mt][3], aAl + off);
        }
#pragma unroll
        for (int nt = 0; nt < 4; nt++) {
            uint32_t off = (uint32_t)((kc * 16 + (lane & 15)) * OPITCH +
                                      (p0l + nt * 8) * 2);
            ldmat2t(bh[nt][0], bh[nt][1], aB + off);
        }
#pragma unroll
        for (int mt = 0; mt < 4; mt++)
#pragma unroll
            for (int nt = 0; nt < 4; nt++)
                mma16816(acc[mt][nt], ah[mt], bh[nt]);
#pragma unroll
        for (int mt = 0; mt < 4; mt++)
#pragma unroll
            for (int nt = 0; nt < 4; nt++)
                mma16816(acc[mt][nt], al[mt], bh[nt]);
    }

#pragma unroll
    for (int mt = 0; mt < 4; mt++) {
        int c = co0 + mt * 16 + (lane >> 2);
        float* o0 = out + ((size_t)(b * CO + c) * LV + l) * HW + hw0 + p0l;
        float* o1 = o0 + (size_t)8 * LV * HW;
#pragma unroll
        for (int nt = 0; nt < 4; nt++) {
            int p = nt * 8 + (lane & 3) * 2;
            *(float2*)(o0 + p) = make_float2(acc[mt][nt][0], acc[mt][nt][1]);
            *(float2*)(o1 + p) = make_float2(acc[mt][nt][2], acc[mt][nt][3]);
        }
    }
}

// ---------------------------------------------------------------------------
extern "C" void kernel_launch(void* const* d_in, const int* in_sizes, int n_in,
                              void* d_out, int out_size) {
    const float* input  = (const float*)d_in[0];
    const float* memory = (const float*)d_in[1];
    const float* wq = (const float*)d_in[2];
    const float* bq = (const float*)d_in[3];
    const float* wk = (const float*)d_in[4];
    const float* bk = (const float*)d_in[5];
    const float* wv = (const float*)d_in[6];
    const float* bv = (const float*)d_in[7];
    float* out = (float*)d_out;

    cudaFuncSetAttribute(convmma_k<3>, cudaFuncAttributeMaxDynamicSharedMemorySize,
                         SMEMSZ);
    cudaFuncSetAttribute(convmma_k<1>, cudaFuncAttributeMaxDynamicSharedMemorySize,
                         SMEMSZ);
    cudaFuncSetAttribute(logits2_k, cudaFuncAttributeMaxDynamicSharedMemorySize,
                         LSMEMSZ);
    cudaFuncSetAttribute(out2_k, cudaFuncAttributeMaxDynamicSharedMemorySize,
                         OSMEM);

    pack_k<<<dim3(BB * LL, 16, 2), 256>>>(input, memory);
    wprep_k<<<(45 * 8192 + 255) / 256, 256>>>(wq, wk, wv);

    convmma_k<3><<<dim3(8, BB * LL), 256, SMEMSZ>>>(bq, 0, LL, 9, 0, 0.5f);
    convmma_k<3><<<dim3(8, BB * LL), 256, SMEMSZ>>>(bk, 1, LL, 9, 0, 1.0f);
    convmma_k<1><<<dim3(8, BB * LV), 256, SMEMSZ>>>(bv, 2, LV, 27, 1, 1.0f);

    logits2_k<<<dim3(9, 16), 256, LSMEMSZ>>>();
    softmax_k<<<256, 256>>>();
    out2_k<<<dim3(128, 8), 256, OSMEM>>>(out);
}

// round 9
// speedup vs baseline: 1.6635x; 1.0985x over previous
#include <cuda_runtime.h>
#include <cuda_fp16.h>
#include <cstdint>

#define BB   8
#define CIN  64
#define CO   128
#define LL   18
#define LV   16
#define HW   1024
#define NH   2

// ---------------- scratch (device globals; no allocation allowed) ----------
__device__ float g_lp[(size_t)9*BB*NH*CO*CO];

__device__ __half g_Qh[(size_t)BB*CO*LL*HW];
__device__ __half g_Ql[(size_t)BB*CO*LL*HW];
__device__ __half g_Kh[(size_t)BB*CO*LL*HW];
__device__ __half g_Kl[(size_t)BB*CO*LL*HW];
__device__ __half g_Vh[(size_t)BB*CO*LV*HW];
__device__ __half g_aH[(size_t)BB*NH*CO*CO];
__device__ __half g_aL[(size_t)BB*NH*CO*CO];

__device__ __half g_hin[(size_t)BB*LL*HW*CIN];
__device__ __half g_lin[(size_t)BB*LL*HW*CIN];
__device__ __half g_hmm[(size_t)BB*LL*HW*CIN];
__device__ __half g_lmm[(size_t)BB*LL*HW*CIN];
__device__ uint4 g_wqh[9*1152],  g_wql[9*1152];
__device__ uint4 g_wkh[9*1152],  g_wkl[9*1152];
__device__ uint4 g_wvh[27*1152], g_wvl[27*1152];

// ---------------- PTX helpers ----------------------------------------------
__device__ __forceinline__ uint32_t smem_u32(const void* p) {
    uint32_t a;
    asm("{ .reg .u64 t; cvta.to.shared.u64 t, %1; cvt.u32.u64 %0, t; }"
        : "=r"(a) : "l"(p));
    return a;
}
__device__ __forceinline__ void ldmat4(uint32_t& r0, uint32_t& r1, uint32_t& r2,
                                       uint32_t& r3, uint32_t a) {
    asm volatile("ldmatrix.sync.aligned.m8n8.x4.shared.b16 {%0,%1,%2,%3}, [%4];"
                 : "=r"(r0), "=r"(r1), "=r"(r2), "=r"(r3) : "r"(a));
}
__device__ __forceinline__ void ldmat2t(uint32_t& r0, uint32_t& r1, uint32_t a) {
    asm volatile("ldmatrix.sync.aligned.m8n8.x2.trans.shared.b16 {%0,%1}, [%2];"
                 : "=r"(r0), "=r"(r1) : "r"(a));
}
__device__ __forceinline__ void mma16816(float* c, const uint32_t* a,
                                         const uint32_t* b) {
    asm volatile(
        "mma.sync.aligned.m16n8k16.row.col.f32.f16.f16.f32 "
        "{%0,%1,%2,%3}, {%4,%5,%6,%7}, {%8,%9}, {%0,%1,%2,%3};"
        : "+f"(c[0]), "+f"(c[1]), "+f"(c[2]), "+f"(c[3])
        : "r"(a[0]), "r"(a[1]), "r"(a[2]), "r"(a[3]), "r"(b[0]), "r"(b[1]));
}
__device__ __forceinline__ void cpasync16(uint32_t dst, const void* src, int sz) {
    asm volatile("cp.async.ca.shared.global [%0], [%1], 16, %2;"
                 :: "r"(dst), "l"(src), "r"(sz) : "memory");
}
__device__ __forceinline__ void cp_commit() {
    asm volatile("cp.async.commit_group;" ::: "memory");
}
__device__ __forceinline__ void cp_wait1() {
    asm volatile("cp.async.wait_group 1;" ::: "memory");
}
__device__ __forceinline__ void cp_wait0() {
    asm volatile("cp.async.wait_group 0;" ::: "memory");
}

__device__ __forceinline__ void emit_split(__half* ph, __half* pl,
                                           float x, float y) {
    __half2 h, l;
    h.x = __float2half_rn(x);
    h.y = __float2half_rn(y);
    l.x = __float2half_rn(x - __half2float(h.x));
    l.y = __float2half_rn(y - __half2float(h.y));
    *(__half2*)ph = h;
    *(__half2*)pl = l;
}

// ---------------- prep kernels ---------------------------------------------
__global__ __launch_bounds__(256) void pack_k(const float* __restrict__ x0,
                                              const float* __restrict__ x1) {
    __shared__ float tile[64][65];
    const int s = blockIdx.x;
    const int hw0 = blockIdx.y * 64;
    const int dst = blockIdx.z;
    const int b = s / LL, l = s % LL;
    const float* x = dst ? x1 : x0;
    __half* oh = dst ? g_hmm : g_hin;
    __half* ol = dst ? g_lmm : g_lin;
#pragma unroll
    for (int i = 0; i < 16; i++) {
        int idx = threadIdx.x + i * 256;
        int ci = idx >> 6, hw = idx & 63;
        tile[ci][hw] = x[(((size_t)b * CIN + ci) * LL + l) * HW + hw0 + hw];
    }
    __syncthreads();
#pragma unroll
    for (int i = 0; i < 16; i++) {
        int idx = threadIdx.x + i * 256;
        int hw = idx >> 6, ci = idx & 63;
        float v = tile[ci][hw];
        __half h = __float2half_rn(v);
        size_t o = ((size_t)s * HW + hw0 + hw) * CIN + ci;
        oh[o] = h;
        ol[o] = __float2half_rn(v - __half2float(h));
    }
}

__global__ __launch_bounds__(256) void wprep_k(const float* __restrict__ wq,
                                               const float* __restrict__ wk,
                                               const float* __restrict__ wv) {
    int i = blockIdx.x * 256 + threadIdx.x;
    if (i >= 45 * 8192) return;
    const float* w;
    __half *oh, *ol;
    int nchunk;
    if (i < 9 * 8192)        { w = wq; oh = (__half*)g_wqh; ol = (__half*)g_wql;
                               nchunk = 9; }
    else if (i < 18 * 8192)  { w = wk; oh = (__half*)g_wkh; ol = (__half*)g_wkl;
                               nchunk = 9; i -= 9 * 8192; }
    else                     { w = wv; oh = (__half*)g_wvh; ol = (__half*)g_wvl;
                               nchunk = 27; i -= 18 * 8192; }
    int c = i >> 13, r = i & 8191, co = r >> 6, ci = r & 63;
    float v = w[(co * 64 + ci) * nchunk + c];
    __half h = __float2half_rn(v);
    __half lo = __float2half_rn(v - __half2float(h));
    oh[(size_t)c * 9216 + co * 72 + ci] = h;
    ol[(size_t)c * 9216 + co * 72 + ci] = lo;
}

// -------- HMMA implicit-GEMM conv, 128co x 128px, 3-stage, k-split ---------
#define ABYTES 18432
#define BUFSZ  73728
#define SMEMSZ (3*BUFSZ)

template<int NPASS>
__device__ __forceinline__ void issue_chunk(
    int c, int is3d, int p0, int b, int l, uint32_t sb,
    const uint4* wh, const uint4* wl,
    const __half* xh, const __half* xl, int tid) {
    int kd, kh, kw;
    if (is3d) { kd = c / 9; int r = c % 9; kh = r / 3; kw = r % 3; }
    else      { kd = 0; kh = c / 3; kw = c % 3; }
    const uint32_t base = sb + (c % 3) * BUFSZ;
    const int acop = (NPASS == 3) ? 2304 : 1152;
#pragma unroll
    for (int i = 0; i < ((NPASS == 3) ? 5 : 3); i++) {
        int idx = tid + i * 512;
        if (idx < acop) {
            int half_ = idx >= 1152;
            int r = idx - half_ * 1152;
            const uint4* s = (half_ ? wl : wh) + (size_t)c * 1152 + r;
            cpasync16(base + half_ * ABYTES + r * 16, s, 16);
        }
    }
    {
        int row, sub, j0, nj;
        if (NPASS > 1) {
            int task = tid >> 1;
            row = task >> 1; sub = task & 1;
            j0 = (tid & 1) * 4; nj = 4;
        } else {
            row = tid >> 2; sub = 0;
            j0 = (tid & 3) * 2; nj = 2;
        }
        int pg = p0 + row;
        int ih = (pg >> 5) + kh - 1, iw = (pg & 31) + kw - 1;
        int ok = ((unsigned)ih < 32u) && ((unsigned)iw < 32u);
        int ihc = ok ? ih : 0, iwc = ok ? iw : 0;
        const __half* s = (sub ? xl : xh) +
            ((size_t)((b * LL + l + kd) * HW) + ihc * 32 + iwc) * CIN;
        uint32_t dst = base + 36864 + sub * ABYTES + row * 144;
        int sz = ok ? 16 : 0;
#pragma unroll
        for (int j = 0; j < 4; j++)
            if (j < nj)
                cpasync16(dst + (j0 + j) * 16, (const char*)s + (j0 + j) * 16, sz);
    }
    cp_commit();
}

template<int NPASS>
__global__ __launch_bounds__(512, 1)
void convmma_k(const float* __restrict__ bias, int mode, int DOUT, int NC,
               int is3d, float scale) {
    extern __shared__ char smem[];
    const uint32_t sb = smem_u32(smem);
    const int tid = threadIdx.x, wid = tid >> 5, lane = tid & 31;
    const int p0 = blockIdx.x * 128;
    const int b = blockIdx.y / DOUT, l = blockIdx.y % DOUT;

    const __half *xh, *xl;
    const uint4 *wh, *wl;
    __half *oph, *opl;
    if (mode == 0)      { xh = g_hin; xl = g_lin; wh = g_wqh; wl = g_wql;
                          oph = g_Qh; opl = g_Ql; }
    else if (mode == 1) { xh = g_hmm; xl = g_lmm; wh = g_wkh; wl = g_wkl;
                          oph = g_Kh; opl = g_Kl; }
    else                { xh = g_hmm; xl = g_lmm; wh = g_wvh; wl = g_wvl;
                          oph = g_Vh; opl = g_Vh; }

    const int kg = wid >> 3;            // k-group: 0 -> k 0,1 ; 1 -> k 2,3
    const int tw = wid & 7;             // tile position
    const int co0 = (tw & 1) * 64;
    const int p0l = (tw >> 1) * 32;

    float acc[4][4][4];
#pragma unroll
    for (int mt = 0; mt < 4; mt++)
#pragma unroll
        for (int nt = 0; nt < 4; nt++)
#pragma unroll
            for (int i = 0; i < 4; i++) acc[mt][nt][i] = 0.f;

    issue_chunk<NPASS>(0, is3d, p0, b, l, sb, wh, wl, xh, xl, tid);
    issue_chunk<NPASS>(1, is3d, p0, b, l, sb, wh, wl, xh, xl, tid);

    const int bnt = (lane >> 4) & 1;
    const int bkh = (lane >> 3) & 1;

    for (int c = 0; c < NC; c++) {
        if (c + 1 < NC) cp_wait1(); else cp_wait0();
        __syncthreads();
        const uint32_t base = sb + (c % 3) * BUFSZ;
        const uint32_t aAh = base, aAl = base + ABYTES;
        const uint32_t aBh = base + 36864, aBl = base + 36864 + ABYTES;
#pragma unroll
        for (int k2 = 0; k2 < 2; k2++) {
            const int k = kg * 2 + k2;
            uint32_t ah[4][4], al[4][4], bh[4][2], bl[4][2];
#pragma unroll
            for (int mt = 0; mt < 4; mt++) {
                uint32_t off = (uint32_t)(((co0 + mt * 16 + (lane & 15)) * 72 +
                                           k * 16 + (lane >> 4) * 8) * 2);
                ldmat4(ah[mt][0], ah[mt][1], ah[mt][2], ah[mt][3], aAh + off);
                if (NPASS == 3)
                    ldmat4(al[mt][0], al[mt][1], al[mt][2], al[mt][3], aAl + off);
            }
#pragma unroll
            for (int pr = 0; pr < 2; pr++) {
                uint32_t off = (uint32_t)(((p0l + (pr * 2 + bnt) * 8 + (lane & 7)) * 72 +
                                           k * 16 + bkh * 8) * 2);
                ldmat4(bh[pr * 2][0], bh[pr * 2][1],
                       bh[pr * 2 + 1][0], bh[pr * 2 + 1][1], aBh + off);
                if (NPASS >= 2)
                    ldmat4(bl[pr * 2][0], bl[pr * 2][1],
                           bl[pr * 2 + 1][0], bl[pr * 2 + 1][1], aBl + off);
            }
#pragma unroll
            for (int mt = 0; mt < 4; mt++)
#pragma unroll
                for (int nt = 0; nt < 4; nt++)
                    mma16816(acc[mt][nt], ah[mt], bh[nt]);
            if (NPASS >= 2) {
#pragma unroll
                for (int mt = 0; mt < 4; mt++)
#pragma unroll
                    for (int nt = 0; nt < 4; nt++)
                        mma16816(acc[mt][nt], ah[mt], bl[nt]);
            }
            if (NPASS == 3) {
#pragma unroll
                for (int mt = 0; mt < 4; mt++)
#pragma unroll
                    for (int nt = 0; nt < 4; nt++)
                        mma16816(acc[mt][nt], al[mt], bh[nt]);
            }
        }
        if (c + 2 < NC)
            issue_chunk<NPASS>(c + 2, is3d, p0, b, l, sb, wh, wl, xh, xl, tid);
    }

    // ---- k-group reduction: kg1 warps dump acc, kg0 warps add + epilogue
    __syncthreads();
    if (kg == 1) {
        char* rb = smem + tw * 8192;
#pragma unroll
        for (int mt = 0; mt < 4; mt++)
#pragma unroll
            for (int nt = 0; nt < 4; nt++)
                *(float4*)(rb + (mt * 4 + nt) * 512 + lane * 16) =
                    *(float4*)acc[mt][nt];
    }
    __syncthreads();
    if (kg == 0) {
        char* rb = smem + tw * 8192;
#pragma unroll
        for (int mt = 0; mt < 4; mt++)
#pragma unroll
            for (int nt = 0; nt < 4; nt++) {
                float4 v = *(float4*)(rb + (mt * 4 + nt) * 512 + lane * 16);
                acc[mt][nt][0] += v.x; acc[mt][nt][1] += v.y;
                acc[mt][nt][2] += v.z; acc[mt][nt][3] += v.w;
            }
#pragma unroll
        for (int mt = 0; mt < 4; mt++) {
            int co = co0 + mt * 16 + (lane >> 2);
            float bv0 = bias[co];
            float bv1 = bias[co + 8];
            size_t o0 = ((size_t)(b * CO + co) * DOUT + l) * HW + p0 + p0l;
            size_t o1 = o0 + (size_t)8 * DOUT * HW;
#pragma unroll
            for (int nt = 0; nt < 4; nt++) {
                int p = nt * 8 + (lane & 3) * 2;
                if (NPASS == 1) {
                    __half2 v0, v1;
                    v0.x = __float2half_rn((acc[mt][nt][0] + bv0) * scale);
                    v0.y = __float2half_rn((acc[mt][nt][1] + bv0) * scale);
                    v1.x = __float2half_rn((acc[mt][nt][2] + bv1) * scale);
                    v1.y = __float2half_rn((acc[mt][nt][3] + bv1) * scale);
                    *(__half2*)(oph + o0 + p) = v0;
                    *(__half2*)(oph + o1 + p) = v1;
                } else {
                    emit_split(oph + o0 + p, opl + o0 + p,
                               (acc[mt][nt][0] + bv0) * scale,
                               (acc[mt][nt][1] + bv0) * scale);
                    emit_split(oph + o1 + p, opl + o1 + p,
                               (acc[mt][nt][2] + bv1) * scale,
                               (acc[mt][nt][3] + bv1) * scale);
                }
            }
        }
    }
}

// ---------------- logits: Q.K^T via HMMA, split-K over 9 l-slices ----------
#define LSMEMSZ (2*BUFSZ)

__global__ __launch_bounds__(256, 1) void logits2_k() {
    extern __shared__ char smem[];
    const uint32_t sb = smem_u32(smem);
    const int tid = threadIdx.x, wid = tid >> 5, lane = tid & 31;
    const int lc = blockIdx.x, bn = blockIdx.y;
    const int b = bn >> 1, n = bn & 1;
    const int l = n * 9 + lc;

    const __half* srcs[4];
    srcs[0] = g_Qh + ((size_t)(b * CO) * LL + l) * HW;
    srcs[1] = g_Ql + ((size_t)(b * CO) * LL + l) * HW;
    srcs[2] = g_Kh + ((size_t)(b * CO) * LL + l) * HW;
    srcs[3] = g_Kl + ((size_t)(b * CO) * LL + l) * HW;

    const int co0 = (wid & 1) * 64;
    const int p0l = (wid >> 1) * 32;
    const int bnt = (lane >> 4) & 1;
    const int bkh = (lane >> 3) & 1;

    float acc[4][4][4];
#pragma unroll
    for (int mt = 0; mt < 4; mt++)
#pragma unroll
        for (int nt = 0; nt < 4; nt++)
#pragma unroll
            for (int i = 0; i < 4; i++) acc[mt][nt][i] = 0.f;

    auto issue = [&](int ch) {
        const uint32_t base = sb + (ch & 1) * BUFSZ;
        const int hw0 = ch * 64;
#pragma unroll
        for (int r = tid; r < 512; r += 256) {
            int plane = r >> 7, c = r & 127;
            const __half* s = srcs[plane] + (size_t)c * (LL * HW) + hw0;
            uint32_t dst = base + plane * ABYTES + c * 144;
#pragma unroll
            for (int j = 0; j < 8; j++)
                cpasync16(dst + j * 16, (const char*)s + j * 16, 16);
        }
        cp_commit();
    };

    issue(0);
    for (int ch = 0; ch < 16; ch++) {
        if (ch + 1 < 16) { issue(ch + 1); cp_wait1(); }
        else             { cp_wait0(); }
        __syncthreads();
        const uint32_t base = sb + (ch & 1) * BUFSZ;
        const uint32_t aAh = base, aAl = base + ABYTES;
        const uint32_t aBh = base + 2 * ABYTES, aBl = base + 3 * ABYTES;
#pragma unroll
        for (int k = 0; k < 4; k++) {
            uint32_t ah[4][4], al[4][4], bh[4][2], bl[4][2];
#pragma unroll
            for (int mt = 0; mt < 4; mt++) {
                uint32_t off = (uint32_t)(((co0 + mt * 16 + (lane & 15)) * 72 +
                                           k * 16 + (lane >> 4) * 8) * 2);
                ldmat4(ah[mt][0], ah[mt][1], ah[mt][2], ah[mt][3], aAh + off);
                ldmat4(al[mt][0], al[mt][1], al[mt][2], al[mt][3], aAl + off);
            }
#pragma unroll
            for (int pr = 0; pr < 2; pr++) {
                uint32_t off = (uint32_t)(((p0l + (pr * 2 + bnt) * 8 + (lane & 7)) * 72 +
                                           k * 16 + bkh * 8) * 2);
                ldmat4(bh[pr * 2][0], bh[pr * 2][1],
                       bh[pr * 2 + 1][0], bh[pr * 2 + 1][1], aBh + off);
                ldmat4(bl[pr * 2][0], bl[pr * 2][1],
                       bl[pr * 2 + 1][0], bl[pr * 2 + 1][1], aBl + off);
            }
#pragma unroll
            for (int mt = 0; mt < 4; mt++)
#pragma unroll
                for (int nt = 0; nt < 4; nt++)
                    mma16816(acc[mt][nt], ah[mt], bh[nt]);
#pragma unroll
            for (int mt = 0; mt < 4; mt++)
#pragma unroll
                for (int nt = 0; nt < 4; nt++)
                    mma16816(acc[mt][nt], ah[mt], bl[nt]);
#pragma unroll
            for (int mt = 0; mt < 4; mt++)
#pragma unroll
                for (int nt = 0; nt < 4; nt++)
                    mma16816(acc[mt][nt], al[mt], bh[nt]);
        }
        __syncthreads();
    }

    float* lp = g_lp + ((size_t)lc * 16 + bn) * CO * CO;
#pragma unroll
    for (int mt = 0; mt < 4; mt++) {
        int c = co0 + mt * 16 + (lane >> 2);
#pragma unroll
        for (int nt = 0; nt < 4; nt++) {
            int m = p0l + nt * 8 + (lane & 3) * 2;
            *(float2*)(lp + (size_t)c * CO + m) =
                make_float2(acc[mt][nt][0], acc[mt][nt][1]);
            *(float2*)(lp + (size_t)(c + 8) * CO + m) =
                make_float2(acc[mt][nt][2], acc[mt][nt][3]);
        }
    }
}

// ---------------- softmax ---------------------------------------------------
__global__ __launch_bounds__(256) void softmax_k() {
    const int warp = (blockIdx.x * 256 + threadIdx.x) >> 5;
    const int lane = threadIdx.x & 31;
    if (warp >= 16 * CO) return;
    const int bn = warp >> 7, c = warp & 127;
    float v[4];
#pragma unroll
    for (int j = 0; j < 4; j++) {
        int m = lane + j * 32;
        float s = 0.f;
#pragma unroll
        for (int p = 0; p < 9; p++)
            s += g_lp[(((size_t)p * 16 + bn) * CO + c) * CO + m];
        v[j] = s;
    }
    float mx = fmaxf(fmaxf(v[0], v[1]), fmaxf(v[2], v[3]));
#pragma unroll
    for (int o = 16; o; o >>= 1) mx = fmaxf(mx, __shfl_xor_sync(0xffffffffu, mx, o));
    float sum = 0.f;
#pragma unroll
    for (int j = 0; j < 4; j++) { v[j] = __expf(v[j] - mx); sum += v[j]; }
#pragma unroll
    for (int o = 16; o; o >>= 1) sum += __shfl_xor_sync(0xffffffffu, sum, o);
    float inv = 1.f / sum;
#pragma unroll
    for (int j = 0; j < 4; j++) {
        float a = v[j] * inv;
        __half h = __float2half_rn(a);
        size_t o = ((size_t)bn * CO + c) * CO + lane + j * 32;
        g_aH[o] = h;
        g_aL[o] = __float2half_rn(a - __half2float(h));
    }
}

// ---------------- out: attn(hi,lo) x V(fp16) via HMMA, 2 passes ------------
#define OPITCH 272
#define OTILE  34816
#define OSMEM  (3*OTILE)

__global__ __launch_bounds__(256, 1) void out2_k(float* __restrict__ out) {
    extern __shared__ char smem[];
    const uint32_t sb = smem_u32(smem);
    const int tid = threadIdx.x, wid = tid >> 5, lane = tid & 31;
    const int pt = blockIdx.x, b = blockIdx.y;
    const int l = pt >> 3;
    const int hw0 = (pt & 7) * 128;
    const int bn = b * 2 + (l >> 3);

    {
        int c = tid & 127;
        if (tid < 128) {
            const __half* s = g_aH + ((size_t)bn * CO + c) * CO;
            uint32_t dst = sb + c * OPITCH;
#pragma unroll
            for (int j = 0; j < 16; j++)
                cpasync16(dst + j * 16, (const char*)s + j * 16, 16);
            const __half* sv = g_Vh + ((size_t)(b * CO + c) * LV + l) * HW + hw0;
            uint32_t dv = sb + 2 * OTILE + c * OPITCH;
#pragma unroll
            for (int j = 0; j < 16; j++)
                cpasync16(dv + j * 16, (const char*)sv + j * 16, 16);
        } else {
            const __half* s = g_aL + ((size_t)bn * CO + c) * CO;
            uint32_t dst = sb + OTILE + c * OPITCH;
#pragma unroll
            for (int j = 0; j < 16; j++)
                cpasync16(dst + j * 16, (const char*)s + j * 16, 16);
        }
    }
    cp_commit();
    cp_wait0();
    __syncthreads();

    const int co0 = (wid & 1) * 64;
    const int p0l = (wid >> 1) * 32;
    const uint32_t aAh = sb, aAl = sb + OTILE;
    const uint32_t aB = sb + 2 * OTILE;

    float acc[4][4][4];
#pragma unroll
    for (int mt = 0; mt < 4; mt++)
#pragma unroll
        for (int nt = 0; nt < 4; nt++)
#pragma unroll
            for (int i = 0; i < 4; i++) acc[mt][nt][i] = 0.f;

#pragma unroll
    for (int kc = 0; kc < 8; kc++) {
        uint32_t ah[4][4], al[4][4], bh[4][2];
#pragma unroll
        for (int mt = 0; mt < 4; mt++) {
            uint32_t off = (uint32_t)((co0 + mt * 16 + (lane & 15)) * OPITCH +
                                      kc * 32 + (lane >> 4) * 16);
            ldmat4(ah[mt][0], ah[mt][1], ah[mt][2], ah[mt][3], aAh + off);
            ldmat4(al[mt][0], al[mt][1], al[mt][2], al[mt][3], aAl + off);
        }
#pragma unroll
        for (int nt = 0; nt < 4; nt++) {
            uint32_t off = (uint32_t)((kc * 16 + (lane & 15)) * OPITCH +
                                      (p0l + nt * 8) * 2);
            ldmat2t(bh[nt][0], bh[nt][1], aB + off);
        }
#pragma unroll
        for (int mt = 0; mt < 4; mt++)
#pragma unroll
            for (int nt = 0; nt < 4; nt++)
                mma16816(acc[mt][nt], ah[mt], bh[nt]);
#pragma unroll
        for (int mt = 0; mt < 4; mt++)
#pragma unroll
            for (int nt = 0; nt < 4; nt++)
                mma16816(acc[mt][nt], al[mt], bh[nt]);
    }

#pragma unroll
    for (int mt = 0; mt < 4; mt++) {
        int c = co0 + mt * 16 + (lane >> 2);
        float* o0 = out + ((size_t)(b * CO + c) * LV + l) * HW + hw0 + p0l;
        float* o1 = o0 + (size_t)8 * LV * HW;
#pragma unroll
        for (int nt = 0; nt < 4; nt++) {
            int p = nt * 8 + (lane & 3) * 2;
            *(float2*)(o0 + p) = make_float2(acc[mt][nt][0], acc[mt][nt][1]);
            *(float2*)(o1 + p) = make_float2(acc[mt][nt][2], acc[mt][nt][3]);
        }
    }
}

// ---------------------------------------------------------------------------
extern "C" void kernel_launch(void* const* d_in, const int* in_sizes, int n_in,
                              void* d_out, int out_size) {
    const float* input  = (const float*)d_in[0];
    const float* memory = (const float*)d_in[1];
    const float* wq = (const float*)d_in[2];
    const float* bq = (const float*)d_in[3];
    const float* wk = (const float*)d_in[4];
    const float* bk = (const float*)d_in[5];
    const float* wv = (const float*)d_in[6];
    const float* bv = (const float*)d_in[7];
    float* out = (float*)d_out;

    cudaFuncSetAttribute(convmma_k<3>, cudaFuncAttributeMaxDynamicSharedMemorySize,
                         SMEMSZ);
    cudaFuncSetAttribute(convmma_k<1>, cudaFuncAttributeMaxDynamicSharedMemorySize,
                         SMEMSZ);
    cudaFuncSetAttribute(logits2_k, cudaFuncAttributeMaxDynamicSharedMemorySize,
                         LSMEMSZ);
    cudaFuncSetAttribute(out2_k, cudaFuncAttributeMaxDynamicSharedMemorySize,
                         OSMEM);

    pack_k<<<dim3(BB * LL, 16, 2), 256>>>(input, memory);
    wprep_k<<<(45 * 8192 + 255) / 256, 256>>>(wq, wk, wv);

    convmma_k<3><<<dim3(8, BB * LL), 512, SMEMSZ>>>(bq, 0, LL, 9, 0, 0.5f);
    convmma_k<3><<<dim3(8, BB * LL), 512, SMEMSZ>>>(bk, 1, LL, 9, 0, 1.0f);
    convmma_k<1><<<dim3(8, BB * LV), 512, SMEMSZ>>>(bv, 2, LV, 27, 1, 1.0f);

    logits2_k<<<dim3(9, 16), 256, LSMEMSZ>>>();
    softmax_k<<<256, 256>>>();
    out2_k<<<dim3(128, 8), 256, OSMEM>>>(out);
}

// round 10
// speedup vs baseline: 1.6680x; 1.0027x over previous
#include <cuda_runtime.h>
#include <cuda_fp16.h>
#include <cstdint>

#define BB   8
#define CIN  64
#define CO   128
#define LL   18
#define LV   16
#define HW   1024
#define NH   2

// ---------------- scratch (device globals; no allocation allowed) ----------
__device__ float g_lp[(size_t)9*BB*NH*CO*CO];

__device__ __half g_Qh[(size_t)BB*CO*LL*HW];
__device__ __half g_Ql[(size_t)BB*CO*LL*HW];
__device__ __half g_Kh[(size_t)BB*CO*LL*HW];
__device__ __half g_Kl[(size_t)BB*CO*LL*HW];
__device__ __half g_Vh[(size_t)BB*CO*LV*HW];
__device__ __half g_aH[(size_t)BB*NH*CO*CO];
__device__ __half g_aL[(size_t)BB*NH*CO*CO];

__device__ __half g_hin[(size_t)BB*LL*HW*CIN];
__device__ __half g_lin[(size_t)BB*LL*HW*CIN];
__device__ __half g_hmm[(size_t)BB*LL*HW*CIN];
__device__ __half g_lmm[(size_t)BB*LL*HW*CIN];
__device__ uint4 g_wqh[9*1152],  g_wql[9*1152];
__device__ uint4 g_wkh[9*1152],  g_wkl[9*1152];
__device__ uint4 g_wvh[27*1152], g_wvl[27*1152];

// ---------------- PTX helpers ----------------------------------------------
__device__ __forceinline__ uint32_t smem_u32(const void* p) {
    uint32_t a;
    asm("{ .reg .u64 t; cvta.to.shared.u64 t, %1; cvt.u32.u64 %0, t; }"
        : "=r"(a) : "l"(p));
    return a;
}
__device__ __forceinline__ void ldmat4(uint32_t& r0, uint32_t& r1, uint32_t& r2,
                                       uint32_t& r3, uint32_t a) {
    asm volatile("ldmatrix.sync.aligned.m8n8.x4.shared.b16 {%0,%1,%2,%3}, [%4];"
                 : "=r"(r0), "=r"(r1), "=r"(r2), "=r"(r3) : "r"(a));
}
__device__ __forceinline__ void ldmat2t(uint32_t& r0, uint32_t& r1, uint32_t a) {
    asm volatile("ldmatrix.sync.aligned.m8n8.x2.trans.shared.b16 {%0,%1}, [%2];"
                 : "=r"(r0), "=r"(r1) : "r"(a));
}
__device__ __forceinline__ void mma16816(float* c, const uint32_t* a,
                                         const uint32_t* b) {
    asm volatile(
        "mma.sync.aligned.m16n8k16.row.col.f32.f16.f16.f32 "
        "{%0,%1,%2,%3}, {%4,%5,%6,%7}, {%8,%9}, {%0,%1,%2,%3};"
        : "+f"(c[0]), "+f"(c[1]), "+f"(c[2]), "+f"(c[3])
        : "r"(a[0]), "r"(a[1]), "r"(a[2]), "r"(a[3]), "r"(b[0]), "r"(b[1]));
}
__device__ __forceinline__ void cpasync16(uint32_t dst, const void* src, int sz) {
    asm volatile("cp.async.ca.shared.global [%0], [%1], 16, %2;"
                 :: "r"(dst), "l"(src), "r"(sz) : "memory");
}
__device__ __forceinline__ void cp_commit() {
    asm volatile("cp.async.commit_group;" ::: "memory");
}
__device__ __forceinline__ void cp_wait1() {
    asm volatile("cp.async.wait_group 1;" ::: "memory");
}
__device__ __forceinline__ void cp_wait0() {
    asm volatile("cp.async.wait_group 0;" ::: "memory");
}

__device__ __forceinline__ void emit_split(__half* ph, __half* pl,
                                           float x, float y) {
    __half2 h, l;
    h.x = __float2half_rn(x);
    h.y = __float2half_rn(y);
    l.x = __float2half_rn(x - __half2float(h.x));
    l.y = __float2half_rn(y - __half2float(h.y));
    *(__half2*)ph = h;
    *(__half2*)pl = l;
}

// ---------------- prep kernels ---------------------------------------------
__global__ __launch_bounds__(256) void pack_k(const float* __restrict__ x0,
                                              const float* __restrict__ x1) {
    __shared__ float tile[64][65];
    const int s = blockIdx.x;
    const int hw0 = blockIdx.y * 64;
    const int dst = blockIdx.z;
    const int b = s / LL, l = s % LL;
    const float* x = dst ? x1 : x0;
    __half* oh = dst ? g_hmm : g_hin;
    __half* ol = dst ? g_lmm : g_lin;
#pragma unroll
    for (int i = 0; i < 16; i++) {
        int idx = threadIdx.x + i * 256;
        int ci = idx >> 6, hw = idx & 63;
        tile[ci][hw] = x[(((size_t)b * CIN + ci) * LL + l) * HW + hw0 + hw];
    }
    __syncthreads();
#pragma unroll
    for (int i = 0; i < 16; i++) {
        int idx = threadIdx.x + i * 256;
        int hw = idx >> 6, ci = idx & 63;
        float v = tile[ci][hw];
        __half h = __float2half_rn(v);
        size_t o = ((size_t)s * HW + hw0 + hw) * CIN + ci;
        oh[o] = h;
        ol[o] = __float2half_rn(v - __half2float(h));
    }
}

__global__ __launch_bounds__(256) void wprep_k(const float* __restrict__ wq,
                                               const float* __restrict__ wk,
                                               const float* __restrict__ wv) {
    int i = blockIdx.x * 256 + threadIdx.x;
    if (i >= 45 * 8192) return;
    const float* w;
    __half *oh, *ol;
    int nchunk;
    if (i < 9 * 8192)        { w = wq; oh = (__half*)g_wqh; ol = (__half*)g_wql;
                               nchunk = 9; }
    else if (i < 18 * 8192)  { w = wk; oh = (__half*)g_wkh; ol = (__half*)g_wkl;
                               nchunk = 9; i -= 9 * 8192; }
    else                     { w = wv; oh = (__half*)g_wvh; ol = (__half*)g_wvl;
                               nchunk = 27; i -= 18 * 8192; }
    int c = i >> 13, r = i & 8191, co = r >> 6, ci = r & 63;
    float v = w[(co * 64 + ci) * nchunk + c];
    __half h = __float2half_rn(v);
    __half lo = __float2half_rn(v - __half2float(h));
    oh[(size_t)c * 9216 + co * 72 + ci] = h;
    ol[(size_t)c * 9216 + co * 72 + ci] = lo;
}

// -------- HMMA implicit-GEMM conv, 128co x 128px, 3-stage, k-split ---------
#define ABYTES 18432
#define BUFSZ  73728
#define SMEMSZ (3*BUFSZ)

template<int NPASS>
__device__ __forceinline__ void issue_chunk(
    int c, int is3d, int p0, int b, int l, uint32_t sb,
    const uint4* wh, const uint4* wl,
    const __half* xh, const __half* xl, int tid) {
    int kd, kh, kw;
    if (is3d) { kd = c / 9; int r = c % 9; kh = r / 3; kw = r % 3; }
    else      { kd = 0; kh = c / 3; kw = c % 3; }
    const uint32_t base = sb + (c % 3) * BUFSZ;
    const int acop = (NPASS == 3) ? 2304 : 1152;
#pragma unroll
    for (int i = 0; i < ((NPASS == 3) ? 5 : 3); i++) {
        int idx = tid + i * 512;
        if (idx < acop) {
            int half_ = idx >= 1152;
            int r = idx - half_ * 1152;
            const uint4* s = (half_ ? wl : wh) + (size_t)c * 1152 + r;
            cpasync16(base + half_ * ABYTES + r * 16, s, 16);
        }
    }
    {
        int row, sub, j0, nj;
        if (NPASS > 1) {
            int task = tid >> 1;
            row = task >> 1; sub = task & 1;
            j0 = (tid & 1) * 4; nj = 4;
        } else {
            row = tid >> 2; sub = 0;
            j0 = (tid & 3) * 2; nj = 2;
        }
        int pg = p0 + row;
        int ih = (pg >> 5) + kh - 1, iw = (pg & 31) + kw - 1;
        int ok = ((unsigned)ih < 32u) && ((unsigned)iw < 32u);
        int ihc = ok ? ih : 0, iwc = ok ? iw : 0;
        const __half* s = (sub ? xl : xh) +
            ((size_t)((b * LL + l + kd) * HW) + ihc * 32 + iwc) * CIN;
        uint32_t dst = base + 36864 + sub * ABYTES + row * 144;
        int sz = ok ? 16 : 0;
#pragma unroll
        for (int j = 0; j < 4; j++)
            if (j < nj)
                cpasync16(dst + (j0 + j) * 16, (const char*)s + (j0 + j) * 16, sz);
    }
    cp_commit();
}

template<int NPASS>
__global__ __launch_bounds__(512, 1)
void convmma_k(const float* __restrict__ bias, int mode, int DOUT, int NC,
               int is3d, float scale) {
    extern __shared__ char smem[];
    const uint32_t sb = smem_u32(smem);
    const int tid = threadIdx.x, wid = tid >> 5, lane = tid & 31;
    const int p0 = blockIdx.x * 128;
    const int b = blockIdx.y / DOUT, l = blockIdx.y % DOUT;

    const __half *xh, *xl;
    const uint4 *wh, *wl;
    __half *oph, *opl;
    if (mode == 0)      { xh = g_hin; xl = g_lin; wh = g_wqh; wl = g_wql;
                          oph = g_Qh; opl = g_Ql; }
    else if (mode == 1) { xh = g_hmm; xl = g_lmm; wh = g_wkh; wl = g_wkl;
                          oph = g_Kh; opl = g_Kl; }
    else                { xh = g_hmm; xl = g_lmm; wh = g_wvh; wl = g_wvl;
                          oph = g_Vh; opl = g_Vh; }

    const int kg = wid >> 3;            // k-group: 0 -> k 0,1 ; 1 -> k 2,3
    const int tw = wid & 7;             // tile position
    const int co0 = (tw & 1) * 64;
    const int p0l = (tw >> 1) * 32;

    float acc[4][4][4];
#pragma unroll
    for (int mt = 0; mt < 4; mt++)
#pragma unroll
        for (int nt = 0; nt < 4; nt++)
#pragma unroll
            for (int i = 0; i < 4; i++) acc[mt][nt][i] = 0.f;

    issue_chunk<NPASS>(0, is3d, p0, b, l, sb, wh, wl, xh, xl, tid);
    issue_chunk<NPASS>(1, is3d, p0, b, l, sb, wh, wl, xh, xl, tid);

    const int bnt = (lane >> 4) & 1;
    const int bkh = (lane >> 3) & 1;

    for (int c = 0; c < NC; c++) {
        if (c + 1 < NC) cp_wait1(); else cp_wait0();
        __syncthreads();
        const uint32_t base = sb + (c % 3) * BUFSZ;
        const uint32_t aAh = base, aAl = base + ABYTES;
        const uint32_t aBh = base + 36864, aBl = base + 36864 + ABYTES;
#pragma unroll
        for (int k2 = 0; k2 < 2; k2++) {
            const int k = kg * 2 + k2;
            // B fragments first (live across all passes): 16 regs
            uint32_t bh[4][2], bl[4][2];
#pragma unroll
            for (int pr = 0; pr < 2; pr++) {
                uint32_t off = (uint32_t)(((p0l + (pr * 2 + bnt) * 8 + (lane & 7)) * 72 +
                                           k * 16 + bkh * 8) * 2);
                ldmat4(bh[pr * 2][0], bh[pr * 2][1],
                       bh[pr * 2 + 1][0], bh[pr * 2 + 1][1], aBh + off);
                if (NPASS >= 2)
                    ldmat4(bl[pr * 2][0], bl[pr * 2][1],
                           bl[pr * 2 + 1][0], bl[pr * 2 + 1][1], aBl + off);
            }
            // A fragments: ONE array reused for hi then lo (peak liveness -16 regs)
            uint32_t a[4][4];
#pragma unroll
            for (int mt = 0; mt < 4; mt++) {
                uint32_t off = (uint32_t)(((co0 + mt * 16 + (lane & 15)) * 72 +
                                           k * 16 + (lane >> 4) * 8) * 2);
                ldmat4(a[mt][0], a[mt][1], a[mt][2], a[mt][3], aAh + off);
            }
#pragma unroll
            for (int mt = 0; mt < 4; mt++)
#pragma unroll
                for (int nt = 0; nt < 4; nt++)
                    mma16816(acc[mt][nt], a[mt], bh[nt]);
            if (NPASS >= 2) {
#pragma unroll
                for (int mt = 0; mt < 4; mt++)
#pragma unroll
                    for (int nt = 0; nt < 4; nt++)
                        mma16816(acc[mt][nt], a[mt], bl[nt]);
            }
            if (NPASS == 3) {
                // overwrite a[] with A-lo (ah now dead -> ptxas reuses regs)
#pragma unroll
                for (int mt = 0; mt < 4; mt++) {
                    uint32_t off = (uint32_t)(((co0 + mt * 16 + (lane & 15)) * 72 +
                                               k * 16 + (lane >> 4) * 8) * 2);
                    ldmat4(a[mt][0], a[mt][1], a[mt][2], a[mt][3], aAl + off);
                }
#pragma unroll
                for (int mt = 0; mt < 4; mt++)
#pragma unroll
                    for (int nt = 0; nt < 4; nt++)
                        mma16816(acc[mt][nt], a[mt], bh[nt]);
            }
        }
        if (c + 2 < NC)
            issue_chunk<NPASS>(c + 2, is3d, p0, b, l, sb, wh, wl, xh, xl, tid);
    }

    // ---- k-group reduction: kg1 warps dump acc, kg0 warps add + epilogue
    __syncthreads();
    if (kg == 1) {
        char* rb = smem + tw * 8192;
#pragma unroll
        for (int mt = 0; mt < 4; mt++)
#pragma unroll
            for (int nt = 0; nt < 4; nt++)
                *(float4*)(rb + (mt * 4 + nt) * 512 + lane * 16) =
                    *(float4*)acc[mt][nt];
    }
    __syncthreads();
    if (kg == 0) {
        char* rb = smem + tw * 8192;
#pragma unroll
        for (int mt = 0; mt < 4; mt++)
#pragma unroll
            for (int nt = 0; nt < 4; nt++) {
                float4 v = *(float4*)(rb + (mt * 4 + nt) * 512 + lane * 16);
                acc[mt][nt][0] += v.x; acc[mt][nt][1] += v.y;
                acc[mt][nt][2] += v.z; acc[mt][nt][3] += v.w;
            }
#pragma unroll
        for (int mt = 0; mt < 4; mt++) {
            int co = co0 + mt * 16 + (lane >> 2);
            float bv0 = bias[co];
            float bv1 = bias[co + 8];
            size_t o0 = ((size_t)(b * CO + co) * DOUT + l) * HW + p0 + p0l;
            size_t o1 = o0 + (size_t)8 * DOUT * HW;
#pragma unroll
            for (int nt = 0; nt < 4; nt++) {
                int p = nt * 8 + (lane & 3) * 2;
                if (NPASS == 1) {
                    __half2 v0, v1;
                    v0.x = __float2half_rn((acc[mt][nt][0] + bv0) * scale);
                    v0.y = __float2half_rn((acc[mt][nt][1] + bv0) * scale);
                    v1.x = __float2half_rn((acc[mt][nt][2] + bv1) * scale);
                    v1.y = __float2half_rn((acc[mt][nt][3] + bv1) * scale);
                    *(__half2*)(oph + o0 + p) = v0;
                    *(__half2*)(oph + o1 + p) = v1;
                } else {
                    emit_split(oph + o0 + p, opl + o0 + p,
                               (acc[mt][nt][0] + bv0) * scale,
                               (acc[mt][nt][1] + bv0) * scale);
                    emit_split(oph + o1 + p, opl + o1 + p,
                               (acc[mt][nt][2] + bv1) * scale,
                               (acc[mt][nt][3] + bv1) * scale);
                }
            }
        }
    }
}

// ---------------- logits: Q.K^T via HMMA, split-K over 9 l-slices ----------
#define LSMEMSZ (2*BUFSZ)

__global__ __launch_bounds__(256, 1) void logits2_k() {
    extern __shared__ char smem[];
    const uint32_t sb = smem_u32(smem);
    const int tid = threadIdx.x, wid = tid >> 5, lane = tid & 31;
    const int lc = blockIdx.x, bn = blockIdx.y;
    const int b = bn >> 1, n = bn & 1;
    const int l = n * 9 + lc;

    const __half* srcs[4];
    srcs[0] = g_Qh + ((size_t)(b * CO) * LL + l) * HW;
    srcs[1] = g_Ql + ((size_t)(b * CO) * LL + l) * HW;
    srcs[2] = g_Kh + ((size_t)(b * CO) * LL + l) * HW;
    srcs[3] = g_Kl + ((size_t)(b * CO) * LL + l) * HW;

    const int co0 = (wid & 1) * 64;
    const int p0l = (wid >> 1) * 32;
    const int bnt = (lane >> 4) & 1;
    const int bkh = (lane >> 3) & 1;

    float acc[4][4][4];
#pragma unroll
    for (int mt = 0; mt < 4; mt++)
#pragma unroll
        for (int nt = 0; nt < 4; nt++)
#pragma unroll
            for (int i = 0; i < 4; i++) acc[mt][nt][i] = 0.f;

    auto issue = [&](int ch) {
        const uint32_t base = sb + (ch & 1) * BUFSZ;
        const int hw0 = ch * 64;
#pragma unroll
        for (int r = tid; r < 512; r += 256) {
            int plane = r >> 7, c = r & 127;
            const __half* s = srcs[plane] + (size_t)c * (LL * HW) + hw0;
            uint32_t dst = base + plane * ABYTES + c * 144;
#pragma unroll
            for (int j = 0; j < 8; j++)
                cpasync16(dst + j * 16, (const char*)s + j * 16, 16);
        }
        cp_commit();
    };

    issue(0);
    for (int ch = 0; ch < 16; ch++) {
        if (ch + 1 < 16) { issue(ch + 1); cp_wait1(); }
        else             { cp_wait0(); }
        __syncthreads();
        const uint32_t base = sb + (ch & 1) * BUFSZ;
        const uint32_t aAh = base, aAl = base + ABYTES;
        const uint32_t aBh = base + 2 * ABYTES, aBl = base + 3 * ABYTES;
#pragma unroll
        for (int k = 0; k < 4; k++) {
            uint32_t bh[4][2], bl[4][2];
#pragma unroll
            for (int pr = 0; pr < 2; pr++) {
                uint32_t off = (uint32_t)(((p0l + (pr * 2 + bnt) * 8 + (lane & 7)) * 72 +
                                           k * 16 + bkh * 8) * 2);
                ldmat4(bh[pr * 2][0], bh[pr * 2][1],
                       bh[pr * 2 + 1][0], bh[pr * 2 + 1][1], aBh + off);
                ldmat4(bl[pr * 2][0], bl[pr * 2][1],
                       bl[pr * 2 + 1][0], bl[pr * 2 + 1][1], aBl + off);
            }
            uint32_t a[4][4];
#pragma unroll
            for (int mt = 0; mt < 4; mt++) {
                uint32_t off = (uint32_t)(((co0 + mt * 16 + (lane & 15)) * 72 +
                                           k * 16 + (lane >> 4) * 8) * 2);
                ldmat4(a[mt][0], a[mt][1], a[mt][2], a[mt][3], aAh + off);
            }
#pragma unroll
            for (int mt = 0; mt < 4; mt++)
#pragma unroll
                for (int nt = 0; nt < 4; nt++)
                    mma16816(acc[mt][nt], a[mt], bh[nt]);
#pragma unroll
            for (int mt = 0; mt < 4; mt++)
#pragma unroll
                for (int nt = 0; nt < 4; nt++)
                    mma16816(acc[mt][nt], a[mt], bl[nt]);
#pragma unroll
            for (int mt = 0; mt < 4; mt++) {
                uint32_t off = (uint32_t)(((co0 + mt * 16 + (lane & 15)) * 72 +
                                           k * 16 + (lane >> 4) * 8) * 2);
                ldmat4(a[mt][0], a[mt][1], a[mt][2], a[mt][3], aAl + off);
            }
#pragma unroll
            for (int mt = 0; mt < 4; mt++)
#pragma unroll
                for (int nt = 0; nt < 4; nt++)
                    mma16816(acc[mt][nt], a[mt], bh[nt]);
        }
        __syncthreads();
    }

    float* lp = g_lp + ((size_t)lc * 16 + bn) * CO * CO;
#pragma unroll
    for (int mt = 0; mt < 4; mt++) {
        int c = co0 + mt * 16 + (lane >> 2);
#pragma unroll
        for (int nt = 0; nt < 4; nt++) {
            int m = p0l + nt * 8 + (lane & 3) * 2;
            *(float2*)(lp + (size_t)c * CO + m) =
                make_float2(acc[mt][nt][0], acc[mt][nt][1]);
            *(float2*)(lp + (size_t)(c + 8) * CO + m) =
                make_float2(acc[mt][nt][2], acc[mt][nt][3]);
        }
    }
}

// ---------------- softmax ---------------------------------------------------
__global__ __launch_bounds__(256) void softmax_k() {
    const int warp = (blockIdx.x * 256 + threadIdx.x) >> 5;
    const int lane = threadIdx.x & 31;
    if (warp >= 16 * CO) return;
    const int bn = warp >> 7, c = warp & 127;
    float v[4];
#pragma unroll
    for (int j = 0; j < 4; j++) {
        int m = lane + j * 32;
        float s = 0.f;
#pragma unroll
        for (int p = 0; p < 9; p++)
            s += g_lp[(((size_t)p * 16 + bn) * CO + c) * CO + m];
        v[j] = s;
    }
    float mx = fmaxf(fmaxf(v[0], v[1]), fmaxf(v[2], v[3]));
#pragma unroll
    for (int o = 16; o; o >>= 1) mx = fmaxf(mx, __shfl_xor_sync(0xffffffffu, mx, o));
    float sum = 0.f;
#pragma unroll
    for (int j = 0; j < 4; j++) { v[j] = __expf(v[j] - mx); sum += v[j]; }
#pragma unroll
    for (int o = 16; o; o >>= 1) sum += __shfl_xor_sync(0xffffffffu, sum, o);
    float inv = 1.f / sum;
#pragma unroll
    for (int j = 0; j < 4; j++) {
        float a = v[j] * inv;
        __half h = __float2half_rn(a);
        size_t o = ((size_t)bn * CO + c) * CO + lane + j * 32;
        g_aH[o] = h;
        g_aL[o] = __float2half_rn(a - __half2float(h));
    }
}

// ---------------- out: attn(hi,lo) x V(fp16) via HMMA, 2 passes ------------
#define OPITCH 272
#define OTILE  34816
#define OSMEM  (3*OTILE)

__global__ __launch_bounds__(256, 1) void out2_k(float* __restrict__ out) {
    extern __shared__ char smem[];
    const uint32_t sb = smem_u32(smem);
    const int tid = threadIdx.x, wid = tid >> 5, lane = tid & 31;
    const int pt = blockIdx.x, b = blockIdx.y;
    const int l = pt >> 3;
    const int hw0 = (pt & 7) * 128;
    const int bn = b * 2 + (l >> 3);

    {
        int c = tid & 127;
        if (tid < 128) {
            const __half* s = g_aH + ((size_t)bn * CO + c) * CO;
            uint32_t dst = sb + c * OPITCH;
#pragma unroll
            for (int j = 0; j < 16; j++)
                cpasync16(dst + j * 16, (const char*)s + j * 16, 16);
            const __half* sv = g_Vh + ((size_t)(b * CO + c) * LV + l) * HW + hw0;
            uint32_t dv = sb + 2 * OTILE + c * OPITCH;
#pragma unroll
            for (int j = 0; j < 16; j++)
                cpasync16(dv + j * 16, (const char*)sv + j * 16, 16);
        } else {
            const __half* s = g_aL + ((size_t)bn * CO + c) * CO;
            uint32_t dst = sb + OTILE + c * OPITCH;
#pragma unroll
            for (int j = 0; j < 16; j++)
                cpasync16(dst + j * 16, (const char*)s + j * 16, 16);
        }
    }
    cp_commit();
    cp_wait0();
    __syncthreads();

    const int co0 = (wid & 1) * 64;
    const int p0l = (wid >> 1) * 32;
    const uint32_t aAh = sb, aAl = sb + OTILE;
    const uint32_t aB = sb + 2 * OTILE;

    float acc[4][4][4];
#pragma unroll
    for (int mt = 0; mt < 4; mt++)
#pragma unroll
        for (int nt = 0; nt < 4; nt++)
#pragma unroll
            for (int i = 0; i < 4; i++) acc[mt][nt][i] = 0.f;

#pragma unroll
    for (int kc = 0; kc < 8; kc++) {
        uint32_t bh[4][2];
#pragma unroll
        for (int nt = 0; nt < 4; nt++) {
            uint32_t off = (uint32_t)((kc * 16 + (lane & 15)) * OPITCH +
                                      (p0l + nt * 8) * 2);
            ldmat2t(bh[nt][0], bh[nt][1], aB + off);
        }
        uint32_t a[4][4];
#pragma unroll
        for (int mt = 0; mt < 4; mt++) {
            uint32_t off = (uint32_t)((co0 + mt * 16 + (lane & 15)) * OPITCH +
                                      kc * 32 + (lane >> 4) * 16);
            ldmat4(a[mt][0], a[mt][1], a[mt][2], a[mt][3], aAh + off);
        }
#pragma unroll
        for (int mt = 0; mt < 4; mt++)
#pragma unroll
            for (int nt = 0; nt < 4; nt++)
                mma16816(acc[mt][nt], a[mt], bh[nt]);
#pragma unroll
        for (int mt = 0; mt < 4; mt++) {
            uint32_t off = (uint32_t)((co0 + mt * 16 + (lane & 15)) * OPITCH +
                                      kc * 32 + (lane >> 4) * 16);
            ldmat4(a[mt][0], a[mt][1], a[mt][2], a[mt][3], aAl + off);
        }
#pragma unroll
        for (int mt = 0; mt < 4; mt++)
#pragma unroll
            for (int nt = 0; nt < 4; nt++)
                mma16816(acc[mt][nt], a[mt], bh[nt]);
    }

#pragma unroll
    for (int mt = 0; mt < 4; mt++) {
        int c = co0 + mt * 16 + (lane >> 2);
        float* o0 = out + ((size_t)(b * CO + c) * LV + l) * HW + hw0 + p0l;
        float* o1 = o0 + (size_t)8 * LV * HW;
#pragma unroll
        for (int nt = 0; nt < 4; nt++) {
            int p = nt * 8 + (lane & 3) * 2;
            *(float2*)(o0 + p) = make_float2(acc[mt][nt][0], acc[mt][nt][1]);
            *(float2*)(o1 + p) = make_float2(acc[mt][nt][2], acc[mt][nt][3]);
        }
    }
}

// ---------------------------------------------------------------------------
extern "C" void kernel_launch(void* const* d_in, const int* in_sizes, int n_in,
                              void* d_out, int out_size) {
    const float* input  = (const float*)d_in[0];
    const float* memory = (const float*)d_in[1];
    const float* wq = (const float*)d_in[2];
    const float* bq = (const float*)d_in[3];
    const float* wk = (const float*)d_in[4];
    const float* bk = (const float*)d_in[5];
    const float* wv = (const float*)d_in[6];
    const float* bv = (const float*)d_in[7];
    float* out = (float*)d_out;

    cudaFuncSetAttribute(convmma_k<3>, cudaFuncAttributeMaxDynamicSharedMemorySize,
                         SMEMSZ);
    cudaFuncSetAttribute(convmma_k<1>, cudaFuncAttributeMaxDynamicSharedMemorySize,
                         SMEMSZ);
    cudaFuncSetAttribute(logits2_k, cudaFuncAttributeMaxDynamicSharedMemorySize,
                         LSMEMSZ);
    cudaFuncSetAttribute(out2_k, cudaFuncAttributeMaxDynamicSharedMemorySize,
                         OSMEM);

    pack_k<<<dim3(BB * LL, 16, 2), 256>>>(input, memory);
    wprep_k<<<(45 * 8192 + 255) / 256, 256>>>(wq, wk, wv);

    convmma_k<3><<<dim3(8, BB * LL), 512, SMEMSZ>>>(bq, 0, LL, 9, 0, 0.5f);
    convmma_k<3><<<dim3(8, BB * LL), 512, SMEMSZ>>>(bk, 1, LL, 9, 0, 1.0f);
    convmma_k<1><<<dim3(8, BB * LV), 512, SMEMSZ>>>(bv, 2, LV, 27, 1, 1.0f);

    logits2_k<<<dim3(9, 16), 256, LSMEMSZ>>>();
    softmax_k<<<256, 256>>>();
    out2_k<<<dim3(128, 8), 256, OSMEM>>>(out);
}

// round 11
// speedup vs baseline: 1.6959x; 1.0167x over previous
#include <cuda_runtime.h>
#include <cuda_fp16.h>
#include <cstdint>

#define BB   8
#define CIN  64
#define CO   128
#define LL   18
#define LV   16
#define HW   1024
#define NH   2

// ---------------- scratch (device globals; no allocation allowed) ----------
__device__ float g_lp[(size_t)9*BB*NH*CO*CO];

__device__ __half g_Qh[(size_t)BB*CO*LL*HW];
__device__ __half g_Ql[(size_t)BB*CO*LL*HW];
__device__ __half g_Kh[(size_t)BB*CO*LL*HW];
__device__ __half g_Kl[(size_t)BB*CO*LL*HW];
__device__ __half g_Vh[(size_t)BB*CO*LV*HW];
__device__ __half g_aH[(size_t)BB*NH*CO*CO];
__device__ __half g_aL[(size_t)BB*NH*CO*CO];

__device__ __half g_hin[(size_t)BB*LL*HW*CIN];
__device__ __half g_lin[(size_t)BB*LL*HW*CIN];
__device__ __half g_hmm[(size_t)BB*LL*HW*CIN];
__device__ __half g_lmm[(size_t)BB*LL*HW*CIN];

// weight images, 32-ci sub-chunks, pitch 40 halves: [sc][co=128][40]
// Q/K: 18 sub-chunks (5120 halves each); V: 54
__device__ uint4 g_wqh[18*640], g_wql[18*640];
__device__ uint4 g_wkh[18*640], g_wkl[18*640];
__device__ uint4 g_wvh[54*640], g_wvl[54*640];

// ---------------- PTX helpers ----------------------------------------------
__device__ __forceinline__ uint32_t smem_u32(const void* p) {
    uint32_t a;
    asm("{ .reg .u64 t; cvta.to.shared.u64 t, %1; cvt.u32.u64 %0, t; }"
        : "=r"(a) : "l"(p));
    return a;
}
__device__ __forceinline__ void ldmat4(uint32_t& r0, uint32_t& r1, uint32_t& r2,
                                       uint32_t& r3, uint32_t a) {
    asm volatile("ldmatrix.sync.aligned.m8n8.x4.shared.b16 {%0,%1,%2,%3}, [%4];"
                 : "=r"(r0), "=r"(r1), "=r"(r2), "=r"(r3) : "r"(a));
}
__device__ __forceinline__ void ldmat2t(uint32_t& r0, uint32_t& r1, uint32_t a) {
    asm volatile("ldmatrix.sync.aligned.m8n8.x2.trans.shared.b16 {%0,%1}, [%2];"
                 : "=r"(r0), "=r"(r1) : "r"(a));
}
__device__ __forceinline__ void mma16816(float* c, const uint32_t* a,
                                         const uint32_t* b) {
    asm volatile(
        "mma.sync.aligned.m16n8k16.row.col.f32.f16.f16.f32 "
        "{%0,%1,%2,%3}, {%4,%5,%6,%7}, {%8,%9}, {%0,%1,%2,%3};"
        : "+f"(c[0]), "+f"(c[1]), "+f"(c[2]), "+f"(c[3])
        : "r"(a[0]), "r"(a[1]), "r"(a[2]), "r"(a[3]), "r"(b[0]), "r"(b[1]));
}
__device__ __forceinline__ void cpasync16(uint32_t dst, const void* src, int sz) {
    asm volatile("cp.async.ca.shared.global [%0], [%1], 16, %2;"
                 :: "r"(dst), "l"(src), "r"(sz) : "memory");
}
__device__ __forceinline__ void cp_commit() {
    asm volatile("cp.async.commit_group;" ::: "memory");
}
__device__ __forceinline__ void cp_wait1() {
    asm volatile("cp.async.wait_group 1;" ::: "memory");
}
__device__ __forceinline__ void cp_wait0() {
    asm volatile("cp.async.wait_group 0;" ::: "memory");
}

__device__ __forceinline__ void emit_split(__half* ph, __half* pl,
                                           float x, float y) {
    __half2 h, l;
    h.x = __float2half_rn(x);
    h.y = __float2half_rn(y);
    l.x = __float2half_rn(x - __half2float(h.x));
    l.y = __float2half_rn(y - __half2float(h.y));
    *(__half2*)ph = h;
    *(__half2*)pl = l;
}

// ---------------- prep kernels ---------------------------------------------
__global__ __launch_bounds__(256) void pack_k(const float* __restrict__ x0,
                                              const float* __restrict__ x1) {
    __shared__ float tile[64][65];
    const int s = blockIdx.x;
    const int hw0 = blockIdx.y * 64;
    const int dst = blockIdx.z;
    const int b = s / LL, l = s % LL;
    const float* x = dst ? x1 : x0;
    __half* oh = dst ? g_hmm : g_hin;
    __half* ol = dst ? g_lmm : g_lin;
#pragma unroll
    for (int i = 0; i < 16; i++) {
        int idx = threadIdx.x + i * 256;
        int ci = idx >> 6, hw = idx & 63;
        tile[ci][hw] = x[(((size_t)b * CIN + ci) * LL + l) * HW + hw0 + hw];
    }
    __syncthreads();
#pragma unroll
    for (int i = 0; i < 16; i++) {
        int idx = threadIdx.x + i * 256;
        int hw = idx >> 6, ci = idx & 63;
        float v = tile[ci][hw];
        __half h = __float2half_rn(v);
        size_t o = ((size_t)s * HW + hw0 + hw) * CIN + ci;
        oh[o] = h;
        ol[o] = __float2half_rn(v - __half2float(h));
    }
}

// 32-ci granular weight images; idx space: (18+18+54)*4096 = 368640
__global__ __launch_bounds__(256) void wprep_k(const float* __restrict__ wq,
                                               const float* __restrict__ wk,
                                               const float* __restrict__ wv) {
    int i = blockIdx.x * 256 + threadIdx.x;
    if (i >= 368640) return;
    const float* w;
    __half *oh, *ol;
    int ntap;
    if (i < 18 * 4096)       { w = wq; oh = (__half*)g_wqh; ol = (__half*)g_wql;
                               ntap = 9; }
    else if (i < 36 * 4096)  { w = wk; oh = (__half*)g_wkh; ol = (__half*)g_wkl;
                               ntap = 9; i -= 18 * 4096; }
    else                     { w = wv; oh = (__half*)g_wvh; ol = (__half*)g_wvl;
                               ntap = 27; i -= 36 * 4096; }
    int sc = i >> 12, r = i & 4095, co = r >> 5, ci32 = r & 31;
    int tap = sc >> 1, chalf = sc & 1;
    int ci = chalf * 32 + ci32;
    float v = w[(co * 64 + ci) * ntap + tap];
    __half h = __float2half_rn(v);
    __half lo = __float2half_rn(v - __half2float(h));
    oh[(size_t)sc * 5120 + co * 40 + ci32] = h;
    ol[(size_t)sc * 5120 + co * 40 + ci32] = lo;
}

// ------ HMMA implicit-GEMM conv, 128co x 128px, 32-ci sub-chunks -----------
// buffer: [Ah 10240][Al 10240 (3p)][Bh][Bl (3p)]; 2 CTAs/SM
#define SMEMSZ3 81920   // 2-stage x 40960
#define SMEMSZ1 61440   // 3-stage x 20480

template<int NPASS, int ST>
__device__ __forceinline__ void issue_chunk(
    int sc, int is3d, int p0, int b, int l, uint32_t sb,
    const uint4* wh, const uint4* wl,
    const __half* xh, const __half* xl, int tid) {
    constexpr uint32_t BUF  = (NPASS == 3) ? 40960u : 20480u;
    constexpr uint32_t BOFF = (NPASS == 3) ? 20480u : 10240u;
    const int tap = sc >> 1, chalf = sc & 1;
    int kd, kh, kw;
    if (is3d) { kd = tap / 9; int r = tap % 9; kh = r / 3; kw = r % 3; }
    else      { kd = 0; kh = tap / 3; kw = tap % 3; }
    const uint32_t base = sb + (uint32_t)(sc % ST) * BUF;
    // A: weights (640 uint4 per plane)
#pragma unroll
    for (int i = 0; i < ((NPASS == 3) ? 5 : 3); i++) {
        int idx = tid + i * 256;
        if (idx < ((NPASS == 3) ? 1280 : 640)) {
            int hf = idx >= 640;
            int r = idx - hf * 640;
            const uint4* s = (hf ? wl : wh) + (size_t)sc * 640 + r;
            cpasync16(base + hf * 10240 + r * 16, s, 16);
        }
    }
    // B: input rows, 64B (32 ci) each
    {
        int row, pl, j0, nj;
        if (NPASS == 3) { pl = tid >> 7; row = tid & 127; j0 = 0; nj = 4; }
        else            { pl = 0; row = tid >> 1; j0 = (tid & 1) * 2; nj = 2; }
        int pg = p0 + row;
        int ih = (pg >> 5) + kh - 1, iw = (pg & 31) + kw - 1;
        int ok = ((unsigned)ih < 32u) && ((unsigned)iw < 32u);
        int ihc = ok ? ih : 0, iwc = ok ? iw : 0;
        const __half* s = (pl ? xl : xh) +
            ((size_t)((b * LL + l + kd) * HW) + ihc * 32 + iwc) * CIN + chalf * 32;
        uint32_t dst = base + BOFF + pl * 10240 + row * 80;
        int sz = ok ? 16 : 0;
#pragma unroll
        for (int j = 0; j < 4; j++)
            if (j < nj)
                cpasync16(dst + (j0 + j) * 16, (const char*)s + (j0 + j) * 16, sz);
    }
    cp_commit();
}

template<int NPASS, int ST>
__global__ __launch_bounds__(256, 2)
void convmma_k(const float* __restrict__ bias, int mode, int DOUT, int NC,
               int is3d, float scale) {
    extern __shared__ char smem[];
    constexpr uint32_t BUF  = (NPASS == 3) ? 40960u : 20480u;
    constexpr uint32_t BOFF = (NPASS == 3) ? 20480u : 10240u;
    const uint32_t sb = smem_u32(smem);
    const int tid = threadIdx.x, wid = tid >> 5, lane = tid & 31;
    const int p0 = blockIdx.x * 128;
    const int b = blockIdx.y / DOUT, l = blockIdx.y % DOUT;

    const __half *xh, *xl;
    const uint4 *wh, *wl;
    __half *oph, *opl;
    if (mode == 0)      { xh = g_hin; xl = g_lin; wh = g_wqh; wl = g_wql;
                          oph = g_Qh; opl = g_Ql; }
    else if (mode == 1) { xh = g_hmm; xl = g_lmm; wh = g_wkh; wl = g_wkl;
                          oph = g_Kh; opl = g_Kl; }
    else                { xh = g_hmm; xl = g_lmm; wh = g_wvh; wl = g_wvl;
                          oph = g_Vh; opl = g_Vh; }

    const int co0 = (wid & 1) * 64;
    const int p0l = (wid >> 1) * 32;
    const int bnt = (lane >> 4) & 1;
    const int bkh = (lane >> 3) & 1;

    float acc[4][4][4];
#pragma unroll
    for (int mt = 0; mt < 4; mt++)
#pragma unroll
        for (int nt = 0; nt < 4; nt++)
#pragma unroll
            for (int i = 0; i < 4; i++) acc[mt][nt][i] = 0.f;

    issue_chunk<NPASS, ST>(0, is3d, p0, b, l, sb, wh, wl, xh, xl, tid);
    issue_chunk<NPASS, ST>(1, is3d, p0, b, l, sb, wh, wl, xh, xl, tid);

    for (int sc = 0; sc < NC; sc++) {
        if (sc + 1 < NC) cp_wait1(); else cp_wait0();
        __syncthreads();
        const uint32_t base = sb + (uint32_t)(sc % ST) * BUF;
        const uint32_t aAh = base, aAl = base + 10240;
        const uint32_t aBh = base + BOFF, aBl = base + BOFF + 10240;
#pragma unroll
        for (int k = 0; k < 2; k++) {
            uint32_t bh[4][2], bl[4][2];
#pragma unroll
            for (int pr = 0; pr < 2; pr++) {
                uint32_t off = (uint32_t)(((p0l + (pr * 2 + bnt) * 8 + (lane & 7)) * 40 +
                                           k * 16 + bkh * 8) * 2);
                ldmat4(bh[pr * 2][0], bh[pr * 2][1],
                       bh[pr * 2 + 1][0], bh[pr * 2 + 1][1], aBh + off);
                if (NPASS >= 2)
                    ldmat4(bl[pr * 2][0], bl[pr * 2][1],
                           bl[pr * 2 + 1][0], bl[pr * 2 + 1][1], aBl + off);
            }
            uint32_t a[4][4];
#pragma unroll
            for (int mt = 0; mt < 4; mt++) {
                uint32_t off = (uint32_t)(((co0 + mt * 16 + (lane & 15)) * 40 +
                                           k * 16 + (lane >> 4) * 8) * 2);
                ldmat4(a[mt][0], a[mt][1], a[mt][2], a[mt][3], aAh + off);
            }
#pragma unroll
            for (int mt = 0; mt < 4; mt++)
#pragma unroll
                for (int nt = 0; nt < 4; nt++)
                    mma16816(acc[mt][nt], a[mt], bh[nt]);
            if (NPASS >= 2) {
#pragma unroll
                for (int mt = 0; mt < 4; mt++)
#pragma unroll
                    for (int nt = 0; nt < 4; nt++)
                        mma16816(acc[mt][nt], a[mt], bl[nt]);
            }
            if (NPASS == 3) {
#pragma unroll
                for (int mt = 0; mt < 4; mt++) {
                    uint32_t off = (uint32_t)(((co0 + mt * 16 + (lane & 15)) * 40 +
                                               k * 16 + (lane >> 4) * 8) * 2);
                    ldmat4(a[mt][0], a[mt][1], a[mt][2], a[mt][3], aAl + off);
                }
#pragma unroll
                for (int mt = 0; mt < 4; mt++)
#pragma unroll
                    for (int nt = 0; nt < 4; nt++)
                        mma16816(acc[mt][nt], a[mt], bh[nt]);
            }
        }
        if (ST == 2) __syncthreads();   // buffer sc%2 is overwritten by sc+2
        if (sc + 2 < NC)
            issue_chunk<NPASS, ST>(sc + 2, is3d, p0, b, l, sb, wh, wl, xh, xl, tid);
    }

    // epilogue
#pragma unroll
    for (int mt = 0; mt < 4; mt++) {
        int co = co0 + mt * 16 + (lane >> 2);
        float bv0 = bias[co];
        float bv1 = bias[co + 8];
        size_t o0 = ((size_t)(b * CO + co) * DOUT + l) * HW + p0 + p0l;
        size_t o1 = o0 + (size_t)8 * DOUT * HW;
#pragma unroll
        for (int nt = 0; nt < 4; nt++) {
            int p = nt * 8 + (lane & 3) * 2;
            if (NPASS == 1) {
                __half2 v0, v1;
                v0.x = __float2half_rn((acc[mt][nt][0] + bv0) * scale);
                v0.y = __float2half_rn((acc[mt][nt][1] + bv0) * scale);
                v1.x = __float2half_rn((acc[mt][nt][2] + bv1) * scale);
                v1.y = __float2half_rn((acc[mt][nt][3] + bv1) * scale);
                *(__half2*)(oph + o0 + p) = v0;
                *(__half2*)(oph + o1 + p) = v1;
            } else {
                emit_split(oph + o0 + p, opl + o0 + p,
                           (acc[mt][nt][0] + bv0) * scale,
                           (acc[mt][nt][1] + bv0) * scale);
                emit_split(oph + o1 + p, opl + o1 + p,
                           (acc[mt][nt][2] + bv1) * scale,
                           (acc[mt][nt][3] + bv1) * scale);
            }
        }
    }
}

// ---------------- logits: Q.K^T via HMMA, split-K over 9 l-slices ----------
#define LAB  18432
#define LBUF 73728
#define LSMEMSZ (2*LBUF)

__global__ __launch_bounds__(256, 1) void logits2_k() {
    extern __shared__ char smem[];
    const uint32_t sb = smem_u32(smem);
    const int tid = threadIdx.x, wid = tid >> 5, lane = tid & 31;
    const int lc = blockIdx.x, bn = blockIdx.y;
    const int b = bn >> 1, n = bn & 1;
    const int l = n * 9 + lc;

    const __half* srcs[4];
    srcs[0] = g_Qh + ((size_t)(b * CO) * LL + l) * HW;
    srcs[1] = g_Ql + ((size_t)(b * CO) * LL + l) * HW;
    srcs[2] = g_Kh + ((size_t)(b * CO) * LL + l) * HW;
    srcs[3] = g_Kl + ((size_t)(b * CO) * LL + l) * HW;

    const int co0 = (wid & 1) * 64;
    const int p0l = (wid >> 1) * 32;
    const int bnt = (lane >> 4) & 1;
    const int bkh = (lane >> 3) & 1;

    float acc[4][4][4];
#pragma unroll
    for (int mt = 0; mt < 4; mt++)
#pragma unroll
        for (int nt = 0; nt < 4; nt++)
#pragma unroll
            for (int i = 0; i < 4; i++) acc[mt][nt][i] = 0.f;

    auto issue = [&](int ch) {
        const uint32_t base = sb + (ch & 1) * LBUF;
        const int hw0 = ch * 64;
#pragma unroll
        for (int r = tid; r < 512; r += 256) {
            int plane = r >> 7, c = r & 127;
            const __half* s = srcs[plane] + (size_t)c * (LL * HW) + hw0;
            uint32_t dst = base + plane * LAB + c * 144;
#pragma unroll
            for (int j = 0; j < 8; j++)
                cpasync16(dst + j * 16, (const char*)s + j * 16, 16);
        }
        cp_commit();
    };

    issue(0);
    for (int ch = 0; ch < 16; ch++) {
        if (ch + 1 < 16) { issue(ch + 1); cp_wait1(); }
        else             { cp_wait0(); }
        __syncthreads();
        const uint32_t base = sb + (ch & 1) * LBUF;
        const uint32_t aAh = base, aAl = base + LAB;
        const uint32_t aBh = base + 2 * LAB, aBl = base + 3 * LAB;
#pragma unroll
        for (int k = 0; k < 4; k++) {
            uint32_t bh[4][2], bl[4][2];
#pragma unroll
            for (int pr = 0; pr < 2; pr++) {
                uint32_t off = (uint32_t)(((p0l + (pr * 2 + bnt) * 8 + (lane & 7)) * 72 +
                                           k * 16 + bkh * 8) * 2);
                ldmat4(bh[pr * 2][0], bh[pr * 2][1],
                       bh[pr * 2 + 1][0], bh[pr * 2 + 1][1], aBh + off);
                ldmat4(bl[pr * 2][0], bl[pr * 2][1],
                       bl[pr * 2 + 1][0], bl[pr * 2 + 1][1], aBl + off);
            }
            uint32_t a[4][4];
#pragma unroll
            for (int mt = 0; mt < 4; mt++) {
                uint32_t off = (uint32_t)(((co0 + mt * 16 + (lane & 15)) * 72 +
                                           k * 16 + (lane >> 4) * 8) * 2);
                ldmat4(a[mt][0], a[mt][1], a[mt][2], a[mt][3], aAh + off);
            }
#pragma unroll
            for (int mt = 0; mt < 4; mt++)
#pragma unroll
                for (int nt = 0; nt < 4; nt++)
                    mma16816(acc[mt][nt], a[mt], bh[nt]);
#pragma unroll
            for (int mt = 0; mt < 4; mt++)
#pragma unroll
                for (int nt = 0; nt < 4; nt++)
                    mma16816(acc[mt][nt], a[mt], bl[nt]);
#pragma unroll
            for (int mt = 0; mt < 4; mt++) {
                uint32_t off = (uint32_t)(((co0 + mt * 16 + (lane & 15)) * 72 +
                                           k * 16 + (lane >> 4) * 8) * 2);
                ldmat4(a[mt][0], a[mt][1], a[mt][2], a[mt][3], aAl + off);
            }
#pragma unroll
            for (int mt = 0; mt < 4; mt++)
#pragma unroll
                for (int nt = 0; nt < 4; nt++)
                    mma16816(acc[mt][nt], a[mt], bh[nt]);
        }
        __syncthreads();
    }

    float* lp = g_lp + ((size_t)lc * 16 + bn) * CO * CO;
#pragma unroll
    for (int mt = 0; mt < 4; mt++) {
        int c = co0 + mt * 16 + (lane >> 2);
#pragma unroll
        for (int nt = 0; nt < 4; nt++) {
            int m = p0l + nt * 8 + (lane & 3) * 2;
            *(float2*)(lp + (size_t)c * CO + m) =
                make_float2(acc[mt][nt][0], acc[mt][nt][1]);
            *(float2*)(lp + (size_t)(c + 8) * CO + m) =
                make_float2(acc[mt][nt][2], acc[mt][nt][3]);
        }
    }
}

// ---------------- softmax ---------------------------------------------------
__global__ __launch_bounds__(256) void softmax_k() {
    const int warp = (blockIdx.x * 256 + threadIdx.x) >> 5;
    const int lane = threadIdx.x & 31;
    if (warp >= 16 * CO) return;
    const int bn = warp >> 7, c = warp & 127;
    float v[4];
#pragma unroll
    for (int j = 0; j < 4; j++) {
        int m = lane + j * 32;
        float s = 0.f;
#pragma unroll
        for (int p = 0; p < 9; p++)
            s += g_lp[(((size_t)p * 16 + bn) * CO + c) * CO + m];
        v[j] = s;
    }
    float mx = fmaxf(fmaxf(v[0], v[1]), fmaxf(v[2], v[3]));
#pragma unroll
    for (int o = 16; o; o >>= 1) mx = fmaxf(mx, __shfl_xor_sync(0xffffffffu, mx, o));
    float sum = 0.f;
#pragma unroll
    for (int j = 0; j < 4; j++) { v[j] = __expf(v[j] - mx); sum += v[j]; }
#pragma unroll
    for (int o = 16; o; o >>= 1) sum += __shfl_xor_sync(0xffffffffu, sum, o);
    float inv = 1.f / sum;
#pragma unroll
    for (int j = 0; j < 4; j++) {
        float a = v[j] * inv;
        __half h = __float2half_rn(a);
        size_t o = ((size_t)bn * CO + c) * CO + lane + j * 32;
        g_aH[o] = h;
        g_aL[o] = __float2half_rn(a - __half2float(h));
    }
}

// ---------------- out: attn(hi,lo) x V(fp16) via HMMA, 2 passes ------------
#define OPITCH 272
#define OTILE  34816
#define OSMEM  (3*OTILE)

__global__ __launch_bounds__(256, 1) void out2_k(float* __restrict__ out) {
    extern __shared__ char smem[];
    const uint32_t sb = smem_u32(smem);
    const int tid = threadIdx.x, wid = tid >> 5, lane = tid & 31;
    const int pt = blockIdx.x, b = blockIdx.y;
    const int l = pt >> 3;
    const int hw0 = (pt & 7) * 128;
    const int bn = b * 2 + (l >> 3);

    {
        int c = tid & 127;
        if (tid < 128) {
            const __half* s = g_aH + ((size_t)bn * CO + c) * CO;
            uint32_t dst = sb + c * OPITCH;
#pragma unroll
            for (int j = 0; j < 16; j++)
                cpasync16(dst + j * 16, (const char*)s + j * 16, 16);
            const __half* sv = g_Vh + ((size_t)(b * CO + c) * LV + l) * HW + hw0;
            uint32_t dv = sb + 2 * OTILE + c * OPITCH;
#pragma unroll
            for (int j = 0; j < 16; j++)
                cpasync16(dv + j * 16, (const char*)sv + j * 16, 16);
        } else {
            const __half* s = g_aL + ((size_t)bn * CO + c) * CO;
            uint32_t dst = sb + OTILE + c * OPITCH;
#pragma unroll
            for (int j = 0; j < 16; j++)
                cpasync16(dst + j * 16, (const char*)s + j * 16, 16);
        }
    }
    cp_commit();
    cp_wait0();
    __syncthreads();

    const int co0 = (wid & 1) * 64;
    const int p0l = (wid >> 1) * 32;
    const uint32_t aAh = sb, aAl = sb + OTILE;
    const uint32_t aB = sb + 2 * OTILE;

    float acc[4][4][4];
#pragma unroll
    for (int mt = 0; mt < 4; mt++)
#pragma unroll
        for (int nt = 0; nt < 4; nt++)
#pragma unroll
            for (int i = 0; i < 4; i++) acc[mt][nt][i] = 0.f;

#pragma unroll
    for (int kc = 0; kc < 8; kc++) {
        uint32_t bh[4][2];
#pragma unroll
        for (int nt = 0; nt < 4; nt++) {
            uint32_t off = (uint32_t)((kc * 16 + (lane & 15)) * OPITCH +
                                      (p0l + nt * 8) * 2);
            ldmat2t(bh[nt][0], bh[nt][1], aB + off);
        }
        uint32_t a[4][4];
#pragma unroll
        for (int mt = 0; mt < 4; mt++) {
            uint32_t off = (uint32_t)((co0 + mt * 16 + (lane & 15)) * OPITCH +
                                      kc * 32 + (lane >> 4) * 16);
            ldmat4(a[mt][0], a[mt][1], a[mt][2], a[mt][3], aAh + off);
        }
#pragma unroll
        for (int mt = 0; mt < 4; mt++)
#pragma unroll
            for (int nt = 0; nt < 4; nt++)
                mma16816(acc[mt][nt], a[mt], bh[nt]);
#pragma unroll
        for (int mt = 0; mt < 4; mt++) {
            uint32_t off = (uint32_t)((co0 + mt * 16 + (lane & 15)) * OPITCH +
                                      kc * 32 + (lane >> 4) * 16);
            ldmat4(a[mt][0], a[mt][1], a[mt][2], a[mt][3], aAl + off);
        }
#pragma unroll
        for (int mt = 0; mt < 4; mt++)
#pragma unroll
            for (int nt = 0; nt < 4; nt++)
                mma16816(acc[mt][nt], a[mt], bh[nt]);
    }

#pragma unroll
    for (int mt = 0; mt < 4; mt++) {
        int c = co0 + mt * 16 + (lane >> 2);
        float* o0 = out + ((size_t)(b * CO + c) * LV + l) * HW + hw0 + p0l;
        float* o1 = o0 + (size_t)8 * LV * HW;
#pragma unroll
        for (int nt = 0; nt < 4; nt++) {
            int p = nt * 8 + (lane & 3) * 2;
            *(float2*)(o0 + p) = make_float2(acc[mt][nt][0], acc[mt][nt][1]);
            *(float2*)(o1 + p) = make_float2(acc[mt][nt][2], acc[mt][nt][3]);
        }
    }
}

// ---------------------------------------------------------------------------
extern "C" void kernel_launch(void* const* d_in, const int* in_sizes, int n_in,
                              void* d_out, int out_size) {
    const float* input  = (const float*)d_in[0];
    const float* memory = (const float*)d_in[1];
    const float* wq = (const float*)d_in[2];
    const float* bq = (const float*)d_in[3];
    const float* wk = (const float*)d_in[4];
    const float* bk = (const float*)d_in[5];
    const float* wv = (const float*)d_in[6];
    const float* bv = (const float*)d_in[7];
    float* out = (float*)d_out;

    cudaFuncSetAttribute((const void*)convmma_k<3, 2>,
                         cudaFuncAttributeMaxDynamicSharedMemorySize, SMEMSZ3);
    cudaFuncSetAttribute((const void*)convmma_k<1, 3>,
                         cudaFuncAttributeMaxDynamicSharedMemorySize, SMEMSZ1);
    cudaFuncSetAttribute((const void*)logits2_k,
                         cudaFuncAttributeMaxDynamicSharedMemorySize, LSMEMSZ);
    cudaFuncSetAttribute((const void*)out2_k,
                         cudaFuncAttributeMaxDynamicSharedMemorySize, OSMEM);

    pack_k<<<dim3(BB * LL, 16, 2), 256>>>(input, memory);
    wprep_k<<<(368640 + 255) / 256, 256>>>(wq, wk, wv);

    convmma_k<3, 2><<<dim3(8, BB * LL), 256, SMEMSZ3>>>(bq, 0, LL, 18, 0, 0.5f);
    convmma_k<3, 2><<<dim3(8, BB * LL), 256, SMEMSZ3>>>(bk, 1, LL, 18, 0, 1.0f);
    convmma_k<1, 3><<<dim3(8, BB * LV), 256, SMEMSZ1>>>(bv, 2, LV, 54, 1, 1.0f);

    logits2_k<<<dim3(9, 16), 256, LSMEMSZ>>>();
    softmax_k<<<256, 256>>>();
    out2_k<<<dim3(128, 8), 256, OSMEM>>>(out);
}